// round 1
// baseline (speedup 1.0000x reference)
#include <cuda_runtime.h>
#include <cuda_bf16.h>
#include <cstdint>

// Problem constants
#define BB 8
#define NN 256
#define BN 2048          // BB*NN
#define EE 16384
#define HH 256
#define NHD 8
#define HD 32
#define VD 8

// ---------------- scratch (static __device__ arrays; no allocations) -------
__device__ float g_xn  [BN*HH];
__device__ float g_q   [BN*HH];
__device__ float g_k   [BN*HH];
__device__ float g_vv  [BN*HH];
__device__ float g_vatt[BN*HH];
__device__ float g_v   [BN*HH];
__device__ float g_dv  [EE*HH];
__device__ float g_vp  [BN*VD*2*HH];   // 16384 x 512
__device__ float g_vsum[BN*HH];
__device__ float g_vj  [EE*HH];
__device__ float g_s12 [EE*2*HH];      // 16384 x 512
__device__ float g_xagg[BN*HH];
__device__ float g_o   [BN*3*HH];      // 2048 x 768
__device__ float g_T   [BN*VD*HH];     // 16384 x 256
__device__ float g_S   [BN*VD*HH];
__device__ float g_ff  [EE*HH];

__device__ __forceinline__ float silu_f(float x) {
    return x / (1.f + __expf(-x));
}

// ---------------- generic SGEMM: C = act(A@B + bias) -----------------------
// A: MxK row-major, B: KxN row-major. M%128==0, N%128==0, K%8==0.
template<bool SILU, bool BIAS>
__global__ __launch_bounds__(256) void sgemm_kernel(
    const float* __restrict__ A, const float* __restrict__ B,
    const float* __restrict__ bias, float* __restrict__ C,
    int M, int N, int K)
{
    __shared__ float As[8][128];
    __shared__ float Bs[8][128];
    const int tid  = threadIdx.x;
    const int tx   = tid & 15;
    const int ty   = tid >> 4;
    const int a_row = tid >> 1;
    const int a_col = (tid & 1) << 2;
    const int b_row = tid >> 5;
    const int b_col = (tid & 31) << 2;
    const float* Ab = A + (size_t)(blockIdx.y * 128) * K;
    const float* Bb = B + blockIdx.x * 128;

    float acc[8][8];
#pragma unroll
    for (int i = 0; i < 8; i++)
#pragma unroll
        for (int j = 0; j < 8; j++) acc[i][j] = 0.f;

    for (int k0 = 0; k0 < K; k0 += 8) {
        float4 av = *reinterpret_cast<const float4*>(Ab + (size_t)a_row * K + k0 + a_col);
        float4 bv = *reinterpret_cast<const float4*>(Bb + (size_t)(k0 + b_row) * N + b_col);
        __syncthreads();
        As[a_col + 0][a_row] = av.x;
        As[a_col + 1][a_row] = av.y;
        As[a_col + 2][a_row] = av.z;
        As[a_col + 3][a_row] = av.w;
        *reinterpret_cast<float4*>(&Bs[b_row][b_col]) = bv;
        __syncthreads();
#pragma unroll
        for (int k = 0; k < 8; k++) {
            float ar[8], br[8];
            *reinterpret_cast<float4*>(ar)     = *reinterpret_cast<const float4*>(&As[k][ty * 8]);
            *reinterpret_cast<float4*>(ar + 4) = *reinterpret_cast<const float4*>(&As[k][ty * 8 + 4]);
            *reinterpret_cast<float4*>(br)     = *reinterpret_cast<const float4*>(&Bs[k][tx * 8]);
            *reinterpret_cast<float4*>(br + 4) = *reinterpret_cast<const float4*>(&Bs[k][tx * 8 + 4]);
#pragma unroll
            for (int i = 0; i < 8; i++)
#pragma unroll
                for (int j = 0; j < 8; j++)
                    acc[i][j] += ar[i] * br[j];
        }
    }

    const int row0 = blockIdx.y * 128 + ty * 8;
    const int col0 = blockIdx.x * 128 + tx * 8;
    float bvals[8];
    if (BIAS) {
#pragma unroll
        for (int j = 0; j < 8; j++) bvals[j] = bias[col0 + j];
    }
#pragma unroll
    for (int i = 0; i < 8; i++) {
#pragma unroll
        for (int j = 0; j < 8; j++) {
            float v = acc[i][j];
            if (BIAS) v += bvals[j];
            if (SILU) v = silu_f(v);
            acc[i][j] = v;
        }
        *reinterpret_cast<float4*>(C + (size_t)(row0 + i) * N + col0)     =
            *reinterpret_cast<float4*>(&acc[i][0]);
        *reinterpret_cast<float4*>(C + (size_t)(row0 + i) * N + col0 + 4) =
            *reinterpret_cast<float4*>(&acc[i][4]);
    }
}

static void run_gemm(const float* A, const float* B, const float* bias, float* C,
                     int M, int N, int K, bool silu_act)
{
    dim3 grid(N / 128, M / 128), block(256);
    if (bias) {
        if (silu_act) sgemm_kernel<true, true><<<grid, block>>>(A, B, bias, C, M, N, K);
        else          sgemm_kernel<false, true><<<grid, block>>>(A, B, bias, C, M, N, K);
    } else {
        if (silu_act) sgemm_kernel<true, false><<<grid, block>>>(A, B, nullptr, C, M, N, K);
        else          sgemm_kernel<false, false><<<grid, block>>>(A, B, nullptr, C, M, N, K);
    }
}

// ---------------- LayerNorm -------------------------------------------------
__global__ __launch_bounds__(256) void ln_kernel(const float* __restrict__ x,
                                                 const float* __restrict__ w,
                                                 const float* __restrict__ b,
                                                 float* __restrict__ xn)
{
    int n = blockIdx.x, h = threadIdx.x;
    __shared__ float red[8];
    float v = x[n * HH + h];
    float s = v;
#pragma unroll
    for (int o = 16; o; o >>= 1) s += __shfl_xor_sync(0xffffffffu, s, o);
    if ((h & 31) == 0) red[h >> 5] = s;
    __syncthreads();
    float tot = 0.f;
#pragma unroll
    for (int i = 0; i < 8; i++) tot += red[i];
    float mu = tot * (1.f / HH);
    float dv = v - mu;
    float s2 = dv * dv;
#pragma unroll
    for (int o = 16; o; o >>= 1) s2 += __shfl_xor_sync(0xffffffffu, s2, o);
    __syncthreads();
    if ((h & 31) == 0) red[h >> 5] = s2;
    __syncthreads();
    float var = 0.f;
#pragma unroll
    for (int i = 0; i < 8; i++) var += red[i];
    var *= (1.f / HH);
    xn[n * HH + h] = dv * rsqrtf(var + 1e-5f) * w[h] + b[h];
}

// ---------------- fused attention: per (b,h) block --------------------------
// out[b,i,h,:] = (sum_j silu(q_i.k_j/sqrt(HD)) * v_j) / N
__global__ __launch_bounds__(256) void attn_kernel(const float* __restrict__ q,
                                                   const float* __restrict__ k,
                                                   const float* __restrict__ vv,
                                                   float* __restrict__ out)
{
    int bh = blockIdx.x;
    int b = bh >> 3, h = bh & 7;
    int i = threadIdx.x;
    __shared__ float ks[64][32];
    __shared__ float vs[64][32];
    float qr[32];
    const float* qrow = q + (size_t)(b * NN + i) * HH + h * HD;
#pragma unroll
    for (int d = 0; d < 32; d++) qr[d] = qrow[d];
    float acc[32];
#pragma unroll
    for (int d = 0; d < 32; d++) acc[d] = 0.f;
    const float scale = rsqrtf((float)HD);

    for (int j0 = 0; j0 < NN; j0 += 64) {
        __syncthreads();
        for (int l = threadIdx.x; l < 512; l += 256) {
            int jr = l >> 3;
            int dc = (l & 7) * 4;
            size_t base = (size_t)(b * NN + j0 + jr) * HH + h * HD + dc;
            *(float4*)&ks[jr][dc] = *(const float4*)&k[base];
            *(float4*)&vs[jr][dc] = *(const float4*)&vv[base];
        }
        __syncthreads();
        for (int j = 0; j < 64; j++) {
            float s = 0.f;
#pragma unroll
            for (int d = 0; d < 32; d++) s += qr[d] * ks[j][d];
            s *= scale;
            s = silu_f(s);
#pragma unroll
            for (int d = 0; d < 32; d++) acc[d] += s * vs[j][d];
        }
    }
    float* orow = out + (size_t)(b * NN + i) * HH + h * HD;
#pragma unroll
    for (int d = 0; d < 32; d++) orow[d] = acc[d] * (1.f / NN);
}

// ---------------- v_j = v[src] * cut * dv -----------------------------------
__global__ __launch_bounds__(256) void vj_kernel(const float* __restrict__ v,
                                                 const float* __restrict__ dv,
                                                 const int* __restrict__ src,
                                                 const float* __restrict__ r,
                                                 float* __restrict__ vj)
{
    int e = blockIdx.x, h = threadIdx.x;
    float rr = r[e];
    float cut = (rr < 5.f) ? 0.5f * (cosf(rr * 0.6283185307179586f) + 1.f) : 0.f;
    vj[(size_t)e * HH + h] = v[(size_t)src[e] * HH + h] * cut * dv[(size_t)e * HH + h];
}

// ---------------- vec_sum over VD of vp[..., :H] -----------------------------
__global__ __launch_bounds__(256) void vecsum_kernel(const float* __restrict__ vp,
                                                     float* __restrict__ vsum)
{
    int n = blockIdx.x, h = threadIdx.x;
    float s = 0.f;
#pragma unroll
    for (int vd = 0; vd < VD; vd++) s += vp[(size_t)(n * VD + vd) * (2 * HH) + h];
    vsum[n * HH + h] = s;
}

// ---------------- scatter: x_agg += v_j ; dvec += vec_j ----------------------
__global__ __launch_bounds__(256) void scatter_kernel(const float* __restrict__ vj,
                                                      const float* __restrict__ s12,
                                                      const float* __restrict__ vec,
                                                      const float* __restrict__ dij,
                                                      const int* __restrict__ src,
                                                      const int* __restrict__ dst,
                                                      float* __restrict__ xagg,
                                                      float* __restrict__ dvec_out)
{
    int e = blockIdx.x, h = threadIdx.x;
    __shared__ float dsh[VD];
    if (h < VD) dsh[h] = dij[e * VD + h];
    __syncthreads();
    int s = src[e], t = dst[e];
    float vje = vj[(size_t)e * HH + h];
    atomicAdd(&xagg[(size_t)t * HH + h], vje);
    float s1  = s12[(size_t)e * (2 * HH) + h];
    float s2v = s12[(size_t)e * (2 * HH) + HH + h];
#pragma unroll
    for (int vd = 0; vd < VD; vd++) {
        float val = vec[(size_t)s * (VD * HH) + vd * HH + h] * s1 + s2v * dsh[vd];
        atomicAdd(&dvec_out[(size_t)t * (VD * HH) + vd * HH + h], val);
    }
}

// ---------------- finalize dx, dvec += vec3*o1 -------------------------------
__global__ __launch_bounds__(256) void finalize_kernel(const float* __restrict__ o,
                                                       const float* __restrict__ vsum,
                                                       const float* __restrict__ vp,
                                                       float* __restrict__ dx,
                                                       float* __restrict__ dvec)
{
    int n = blockIdx.x, h = threadIdx.x;
    float o1 = o[(size_t)n * (3 * HH) + h];
    float o2 = o[(size_t)n * (3 * HH) + HH + h];
    float o3 = o[(size_t)n * (3 * HH) + 2 * HH + h];
    dx[n * HH + h] = vsum[n * HH + h] * o2 + o3;
#pragma unroll
    for (int vd = 0; vd < VD; vd++) {
        float vec3 = vp[(size_t)(n * VD + vd) * (2 * HH) + HH + h];
        dvec[(size_t)n * (VD * HH) + vd * HH + h] += vec3 * o1;
    }
}

// ---------------- w_dot + df_ij ---------------------------------------------
__global__ __launch_bounds__(256) void wdot_kernel(const float* __restrict__ T,
                                                   const float* __restrict__ S,
                                                   const float* __restrict__ ff,
                                                   const float* __restrict__ dij,
                                                   const int* __restrict__ src,
                                                   const int* __restrict__ dst,
                                                   float* __restrict__ df)
{
    int e = blockIdx.x, h = threadIdx.x;
    __shared__ float dsh[VD];
    if (h < VD) dsh[h] = dij[e * VD + h];
    __syncthreads();
    int s = src[e], t = dst[e];
    float tv[VD], sv[VD];
    float pT = 0.f, pS = 0.f;
#pragma unroll
    for (int vd = 0; vd < VD; vd++) {
        tv[vd] = T[(size_t)(t * VD + vd) * HH + h];
        sv[vd] = S[(size_t)(s * VD + vd) * HH + h];
        pT += tv[vd] * dsh[vd];
        pS += sv[vd] * dsh[vd];
    }
    float wd = 0.f;
#pragma unroll
    for (int vd = 0; vd < VD; vd++)
        wd += (tv[vd] - pT * dsh[vd]) * (sv[vd] - pS * dsh[vd]);
    df[(size_t)e * HH + h] = ff[(size_t)e * HH + h] * wd;
}

// ---------------- launcher ---------------------------------------------------
extern "C" void kernel_launch(void* const* d_in, const int* in_sizes, int n_in,
                              void* d_out, int out_size)
{
    const float* x    = (const float*)d_in[0];
    const float* vec  = (const float*)d_in[1];
    const int*   ei   = (const int*)d_in[2];
    const float* r_ij = (const float*)d_in[3];
    const float* f_ij = (const float*)d_in[4];
    const float* d_ij = (const float*)d_in[5];
    // d_in[6] = batch (unused)
    const float* ln_w = (const float*)d_in[7];
    const float* ln_b = (const float*)d_in[8];
    const float* Wq   = (const float*)d_in[9];
    const float* Wk   = (const float*)d_in[10];
    const float* Wv   = (const float*)d_in[11];
    const float* Wao  = (const float*)d_in[12];
    const float* Wvec = (const float*)d_in[13];
    const float* Wdv  = (const float*)d_in[14];
    const float* bdv  = (const float*)d_in[15];
    const float* Ws   = (const float*)d_in[16];
    const float* bs   = (const float*)d_in[17];
    const float* Wo   = (const float*)d_in[18];
    const float* bo   = (const float*)d_in[19];
    const float* Wf   = (const float*)d_in[20];
    const float* bf   = (const float*)d_in[21];
    const float* Wsrc = (const float*)d_in[22];
    const float* Wtrg = (const float*)d_in[23];

    const int* src = ei;
    const int* dst = ei + EE;

    float* out      = (float*)d_out;
    float* out_dx   = out;                       // 2048*256
    float* out_dvec = out + (size_t)BN * HH;     // 2048*8*256
    float* out_df   = out_dvec + (size_t)BN * VD * HH; // 16384*256

    // resolve scratch symbols
    float *p_xn, *p_q, *p_k, *p_vv, *p_vatt, *p_v, *p_dv, *p_vp, *p_vsum,
          *p_vj, *p_s12, *p_xagg, *p_o, *p_T, *p_S, *p_ff;
    cudaGetSymbolAddress((void**)&p_xn,   g_xn);
    cudaGetSymbolAddress((void**)&p_q,    g_q);
    cudaGetSymbolAddress((void**)&p_k,    g_k);
    cudaGetSymbolAddress((void**)&p_vv,   g_vv);
    cudaGetSymbolAddress((void**)&p_vatt, g_vatt);
    cudaGetSymbolAddress((void**)&p_v,    g_v);
    cudaGetSymbolAddress((void**)&p_dv,   g_dv);
    cudaGetSymbolAddress((void**)&p_vp,   g_vp);
    cudaGetSymbolAddress((void**)&p_vsum, g_vsum);
    cudaGetSymbolAddress((void**)&p_vj,   g_vj);
    cudaGetSymbolAddress((void**)&p_s12,  g_s12);
    cudaGetSymbolAddress((void**)&p_xagg, g_xagg);
    cudaGetSymbolAddress((void**)&p_o,    g_o);
    cudaGetSymbolAddress((void**)&p_T,    g_T);
    cudaGetSymbolAddress((void**)&p_S,    g_S);
    cudaGetSymbolAddress((void**)&p_ff,   g_ff);

    // 1. LayerNorm
    ln_kernel<<<BN, 256>>>(x, ln_w, ln_b, p_xn);

    // 2. q/k/v projections
    run_gemm(p_xn, Wq, nullptr, p_q,  BN, HH, HH, false);
    run_gemm(p_xn, Wk, nullptr, p_k,  BN, HH, HH, false);
    run_gemm(p_xn, Wv, nullptr, p_vv, BN, HH, HH, false);

    // 3. fused attention
    attn_kernel<<<BB * NHD, 256>>>(p_q, p_k, p_vv, p_vatt);

    // 4. output projection of attention
    run_gemm(p_vatt, Wao, nullptr, p_v, BN, HH, HH, false);

    // 5. dv = silu(f_ij@Wdv + bdv)
    run_gemm(f_ij, Wdv, bdv, p_dv, EE, HH, HH, true);

    // 6. v_j
    vj_kernel<<<EE, 256>>>(p_v, p_dv, src, r_ij, p_vj);

    // 7. s12 = silu(v_j@Ws + bs)
    run_gemm(p_vj, Ws, bs, p_s12, EE, 2 * HH, HH, true);

    // 8. vp = vec@Wvec
    run_gemm(vec, Wvec, nullptr, p_vp, BN * VD, 2 * HH, HH, false);

    // 9. vec_sum
    vecsum_kernel<<<BN, 256>>>(p_vp, p_vsum);

    // 10. zero accumulators
    cudaMemsetAsync(p_xagg, 0, (size_t)BN * HH * sizeof(float), 0);
    cudaMemsetAsync(out_dvec, 0, (size_t)BN * VD * HH * sizeof(float), 0);

    // 11. scatter-add
    scatter_kernel<<<EE, 256>>>(p_vj, p_s12, vec, d_ij, src, dst, p_xagg, out_dvec);

    // 12. o = x_agg@Wo + bo
    run_gemm(p_xagg, Wo, bo, p_o, BN, 3 * HH, HH, false);

    // 13. dx, dvec += vec3*o1
    finalize_kernel<<<BN, 256>>>(p_o, p_vsum, p_vp, out_dx, out_dvec);

    // 14. node-level T/S (algebraic hoist of per-edge GEMMs)
    run_gemm(vec, Wtrg, nullptr, p_T, BN * VD, HH, HH, false);
    run_gemm(vec, Wsrc, nullptr, p_S, BN * VD, HH, HH, false);

    // 15. ff = silu(f_ij@Wf + bf)
    run_gemm(f_ij, Wf, bf, p_ff, EE, HH, HH, true);

    // 16. w_dot + df_ij
    wdot_kernel<<<EE, 256>>>(p_T, p_S, p_ff, d_ij, src, dst, out_df);
}

// round 2
// speedup vs baseline: 1.2150x; 1.2150x over previous
#include <cuda_runtime.h>
#include <cuda_bf16.h>
#include <cstdint>

// Problem constants
#define BB 8
#define NN 256
#define BN 2048          // BB*NN
#define EE 16384
#define HH 256
#define NHD 8
#define HD 32
#define VD 8

// ---------------- scratch (static __device__ arrays; no allocations) -------
__device__ float g_xn  [BN*HH];
__device__ float g_q   [BN*HH];
__device__ float g_k   [BN*HH];
__device__ float g_vv  [BN*HH];
__device__ float g_vatt[BN*HH];
__device__ float g_v   [BN*HH];
__device__ float g_dv  [EE*HH];
__device__ float g_vp  [BN*VD*2*HH];   // 16384 x 512
__device__ float g_vj  [EE*HH];
__device__ float g_s12 [EE*2*HH];      // 16384 x 512
__device__ float g_xagg[BN*HH];
__device__ float g_o   [BN*3*HH];      // 2048 x 768
__device__ float g_T   [BN*VD*HH];     // 16384 x 256
__device__ float g_S   [BN*VD*HH];
__device__ float g_ff  [EE*HH];

__device__ __forceinline__ float silu_f(float x) {
    return x / (1.f + __expf(-x));
}

// ---------------- batched SGEMM: C[z] = act(A@B[z] + bias[z]) ---------------
// A: MxK row-major (shared across z), B: KxN row-major. 256 threads.
// Tile BM x BNt, K-step 8, double-buffered smem, packed fma.rn.f32x2 math.
struct Batch3 {
    const float* B[3];
    const float* bias[3];
    float* C[3];
};

template<int BM, int BNt, bool SILU, bool BIAS>
__global__ __launch_bounds__(256) void sgemm_kernel(
    const float* __restrict__ A, Batch3 gb, int M, int N, int K)
{
    constexpr int RM  = BM  / 16;          // rows per thread (8 or 4)
    constexpr int RN  = BNt / 16;          // cols per thread (8 or 4)
    constexpr int ELA = BM  * 8 / 256;     // A floats loaded per thread per k-step
    constexpr int ELB = BNt * 8 / 256;

    __shared__ float As[2][8][BM];
    __shared__ float Bs[2][8][BNt];

    const int z = blockIdx.z;
    const float* __restrict__ Bp   = gb.B[z];
    const float* __restrict__ bias = gb.bias[z];
    float*       __restrict__ C    = gb.C[z];

    const int tid = threadIdx.x;
    const int tx  = tid & 15;
    const int ty  = tid >> 4;

    int a_row, a_col, b_row, b_col;
    if (ELA == 4) { a_row = tid >> 1; a_col = (tid & 1) * 4; }
    else          { a_row = tid >> 2; a_col = (tid & 3) * 2; }
    b_row = tid >> 5;
    if (ELB == 4) { b_col = (tid & 31) * 4; }
    else          { b_col = (tid & 31) * 2; }

    const float* Ab = A  + (size_t)(blockIdx.y * BM + a_row) * K + a_col;
    const float* Bb = Bp + (size_t)b_row * N + blockIdx.x * BNt + b_col;

    float pa[ELA], pb[ELB];
    unsigned long long acc2[RM][RN / 2];
#pragma unroll
    for (int i = 0; i < RM; i++)
#pragma unroll
        for (int j = 0; j < RN / 2; j++) acc2[i][j] = 0ull;

#define LOAD_AB(k0) do {                                                     \
        if constexpr (ELA == 4) *(float4*)pa = *(const float4*)(Ab + (k0));  \
        else                    *(float2*)pa = *(const float2*)(Ab + (k0));  \
        if constexpr (ELB == 4) *(float4*)pb = *(const float4*)(Bb + (size_t)(k0) * N); \
        else                    *(float2*)pb = *(const float2*)(Bb + (size_t)(k0) * N); \
    } while (0)

#define STORE_AB(buf) do {                                                   \
        _Pragma("unroll")                                                    \
        for (int i = 0; i < ELA; i++) As[buf][a_col + i][a_row] = pa[i];     \
        if constexpr (ELB == 4) *(float4*)&Bs[buf][b_row][b_col] = *(float4*)pb; \
        else                    *(float2*)&Bs[buf][b_row][b_col] = *(float2*)pb; \
    } while (0)

#define COMPUTE(buf) do {                                                    \
        _Pragma("unroll")                                                    \
        for (int k = 0; k < 8; k++) {                                        \
            float ar[RM];                                                    \
            if constexpr (RM == 8) {                                         \
                *(float4*)ar       = *(const float4*)&As[buf][k][ty * 8];    \
                *(float4*)(ar + 4) = *(const float4*)&As[buf][k][ty * 8 + 4];\
            } else {                                                         \
                *(float4*)ar       = *(const float4*)&As[buf][k][ty * 4];    \
            }                                                                \
            unsigned long long br2[RN / 2];                                  \
            if constexpr (RN == 8) {                                         \
                *(float4*)&br2[0] = *(const float4*)&Bs[buf][k][tx * 8];     \
                *(float4*)&br2[2] = *(const float4*)&Bs[buf][k][tx * 8 + 4]; \
            } else {                                                         \
                *(float4*)&br2[0] = *(const float4*)&Bs[buf][k][tx * 4];     \
            }                                                                \
            _Pragma("unroll")                                                \
            for (int i = 0; i < RM; i++) {                                   \
                unsigned long long a2;                                       \
                asm("mov.b64 %0, {%1, %1};" : "=l"(a2)                       \
                    : "r"(__float_as_uint(ar[i])));                          \
                _Pragma("unroll")                                            \
                for (int jp = 0; jp < RN / 2; jp++)                          \
                    asm("fma.rn.f32x2 %0, %1, %2, %0;"                       \
                        : "+l"(acc2[i][jp]) : "l"(a2), "l"(br2[jp]));        \
            }                                                                \
        }                                                                    \
    } while (0)

    LOAD_AB(0);
    STORE_AB(0);
    __syncthreads();

    int buf = 0;
    for (int k0 = 8; k0 <= K; k0 += 8) {
        if (k0 < K) LOAD_AB(k0);
        COMPUTE(buf);
        if (k0 < K) {
            STORE_AB(buf ^ 1);
            buf ^= 1;
            __syncthreads();
        }
    }

#undef LOAD_AB
#undef STORE_AB
#undef COMPUTE

    const int row0 = blockIdx.y * BM  + ty * RM;
    const int col0 = blockIdx.x * BNt + tx * RN;
    float bvals[RN];
    if (BIAS) {
#pragma unroll
        for (int j = 0; j < RN; j++) bvals[j] = bias[col0 + j];
    }
#pragma unroll
    for (int i = 0; i < RM; i++) {
        float* accf = (float*)acc2[i];
#pragma unroll
        for (int j = 0; j < RN; j++) {
            float v = accf[j];
            if (BIAS) v += bvals[j];
            if (SILU) v = silu_f(v);
            accf[j] = v;
        }
        *(float4*)(C + (size_t)(row0 + i) * N + col0) = *(float4*)&accf[0];
        if (RN == 8)
            *(float4*)(C + (size_t)(row0 + i) * N + col0 + 4) = *(float4*)&accf[4];
    }
}

// helpers for single-target launches
static Batch3 one(const float* B, const float* bias, float* C) {
    Batch3 g{};
    g.B[0] = B; g.bias[0] = bias; g.C[0] = C;
    return g;
}

// ---------------- LayerNorm -------------------------------------------------
__global__ __launch_bounds__(256) void ln_kernel(const float* __restrict__ x,
                                                 const float* __restrict__ w,
                                                 const float* __restrict__ b,
                                                 float* __restrict__ xn)
{
    int n = blockIdx.x, h = threadIdx.x;
    __shared__ float red[8];
    float v = x[n * HH + h];
    float s = v;
#pragma unroll
    for (int o = 16; o; o >>= 1) s += __shfl_xor_sync(0xffffffffu, s, o);
    if ((h & 31) == 0) red[h >> 5] = s;
    __syncthreads();
    float tot = 0.f;
#pragma unroll
    for (int i = 0; i < 8; i++) tot += red[i];
    float mu = tot * (1.f / HH);
    float dv = v - mu;
    float s2 = dv * dv;
#pragma unroll
    for (int o = 16; o; o >>= 1) s2 += __shfl_xor_sync(0xffffffffu, s2, o);
    __syncthreads();
    if ((h & 31) == 0) red[h >> 5] = s2;
    __syncthreads();
    float var = 0.f;
#pragma unroll
    for (int i = 0; i < 8; i++) var += red[i];
    var *= (1.f / HH);
    xn[n * HH + h] = dv * rsqrtf(var + 1e-5f) * w[h] + b[h];
}

// ---------------- fused attention: 2 blocks per (b,h), 128 threads ----------
__global__ __launch_bounds__(128) void attn_kernel(const float* __restrict__ q,
                                                   const float* __restrict__ k,
                                                   const float* __restrict__ vv,
                                                   float* __restrict__ out)
{
    int blk = blockIdx.x;
    int b = blk >> 4;
    int h = (blk >> 1) & 7;
    int i = (blk & 1) * 128 + threadIdx.x;
    __shared__ float ks[64][32];
    __shared__ float vs[64][32];
    float qr[32];
    const float* qrow = q + (size_t)(b * NN + i) * HH + h * HD;
#pragma unroll
    for (int d = 0; d < 32; d++) qr[d] = qrow[d];
    float acc[32];
#pragma unroll
    for (int d = 0; d < 32; d++) acc[d] = 0.f;
    const float scale = rsqrtf((float)HD);

    for (int j0 = 0; j0 < NN; j0 += 64) {
        __syncthreads();
        for (int l = threadIdx.x; l < 512; l += 128) {
            int jr = l >> 3;
            int dc = (l & 7) * 4;
            size_t base = (size_t)(b * NN + j0 + jr) * HH + h * HD + dc;
            *(float4*)&ks[jr][dc] = *(const float4*)&k[base];
            *(float4*)&vs[jr][dc] = *(const float4*)&vv[base];
        }
        __syncthreads();
        for (int j = 0; j < 64; j++) {
            float s = 0.f;
#pragma unroll
            for (int d = 0; d < 32; d++) s += qr[d] * ks[j][d];
            s *= scale;
            s = silu_f(s);
#pragma unroll
            for (int d = 0; d < 32; d++) acc[d] += s * vs[j][d];
        }
    }
    float* orow = out + (size_t)(b * NN + i) * HH + h * HD;
#pragma unroll
    for (int d = 0; d < 32; d++) orow[d] = acc[d] * (1.f / NN);
}

// ---------------- v_j = v[src] * cut * dv -----------------------------------
__global__ __launch_bounds__(256) void vj_kernel(const float* __restrict__ v,
                                                 const float* __restrict__ dv,
                                                 const int* __restrict__ src,
                                                 const float* __restrict__ r,
                                                 float* __restrict__ vj)
{
    int e = blockIdx.x, h = threadIdx.x;
    float rr = r[e];
    float cut = (rr < 5.f) ? 0.5f * (cosf(rr * 0.6283185307179586f) + 1.f) : 0.f;
    vj[(size_t)e * HH + h] = v[(size_t)src[e] * HH + h] * cut * dv[(size_t)e * HH + h];
}

// ---------------- scatter: x_agg += v_j ; dvec += vec_j ----------------------
__global__ __launch_bounds__(256) void scatter_kernel(const float* __restrict__ vj,
                                                      const float* __restrict__ s12,
                                                      const float* __restrict__ vec,
                                                      const float* __restrict__ dij,
                                                      const int* __restrict__ src,
                                                      const int* __restrict__ dst,
                                                      float* __restrict__ xagg,
                                                      float* __restrict__ dvec_out)
{
    int e = blockIdx.x, h = threadIdx.x;
    __shared__ float dsh[VD];
    if (h < VD) dsh[h] = dij[e * VD + h];
    __syncthreads();
    int s = src[e], t = dst[e];
    float vje = vj[(size_t)e * HH + h];
    atomicAdd(&xagg[(size_t)t * HH + h], vje);
    float s1  = s12[(size_t)e * (2 * HH) + h];
    float s2v = s12[(size_t)e * (2 * HH) + HH + h];
#pragma unroll
    for (int vd = 0; vd < VD; vd++) {
        float val = vec[(size_t)s * (VD * HH) + vd * HH + h] * s1 + s2v * dsh[vd];
        atomicAdd(&dvec_out[(size_t)t * (VD * HH) + vd * HH + h], val);
    }
}

// ---------------- finalize: dx = vecsum*o2+o3, dvec += vec3*o1 ---------------
__global__ __launch_bounds__(256) void finalize_kernel(const float* __restrict__ o,
                                                       const float* __restrict__ vp,
                                                       float* __restrict__ dx,
                                                       float* __restrict__ dvec)
{
    int n = blockIdx.x, h = threadIdx.x;
    float o1 = o[(size_t)n * (3 * HH) + h];
    float o2 = o[(size_t)n * (3 * HH) + HH + h];
    float o3 = o[(size_t)n * (3 * HH) + 2 * HH + h];
    float vsum = 0.f;
#pragma unroll
    for (int vd = 0; vd < VD; vd++)
        vsum += vp[(size_t)(n * VD + vd) * (2 * HH) + h];
    dx[n * HH + h] = vsum * o2 + o3;
#pragma unroll
    for (int vd = 0; vd < VD; vd++) {
        float vec3 = vp[(size_t)(n * VD + vd) * (2 * HH) + HH + h];
        dvec[(size_t)n * (VD * HH) + vd * HH + h] += vec3 * o1;
    }
}

// ---------------- w_dot + df_ij ---------------------------------------------
__global__ __launch_bounds__(256) void wdot_kernel(const float* __restrict__ T,
                                                   const float* __restrict__ S,
                                                   const float* __restrict__ ff,
                                                   const float* __restrict__ dij,
                                                   const int* __restrict__ src,
                                                   const int* __restrict__ dst,
                                                   float* __restrict__ df)
{
    int e = blockIdx.x, h = threadIdx.x;
    __shared__ float dsh[VD];
    if (h < VD) dsh[h] = dij[e * VD + h];
    __syncthreads();
    int s = src[e], t = dst[e];
    float tv[VD], sv[VD];
    float pT = 0.f, pS = 0.f;
#pragma unroll
    for (int vd = 0; vd < VD; vd++) {
        tv[vd] = T[(size_t)(t * VD + vd) * HH + h];
        sv[vd] = S[(size_t)(s * VD + vd) * HH + h];
        pT += tv[vd] * dsh[vd];
        pS += sv[vd] * dsh[vd];
    }
    float wd = 0.f;
#pragma unroll
    for (int vd = 0; vd < VD; vd++)
        wd += (tv[vd] - pT * dsh[vd]) * (sv[vd] - pS * dsh[vd]);
    df[(size_t)e * HH + h] = ff[(size_t)e * HH + h] * wd;
}

// ---------------- launcher ---------------------------------------------------
extern "C" void kernel_launch(void* const* d_in, const int* in_sizes, int n_in,
                              void* d_out, int out_size)
{
    const float* x    = (const float*)d_in[0];
    const float* vec  = (const float*)d_in[1];
    const int*   ei   = (const int*)d_in[2];
    const float* r_ij = (const float*)d_in[3];
    const float* f_ij = (const float*)d_in[4];
    const float* d_ij = (const float*)d_in[5];
    const float* ln_w = (const float*)d_in[7];
    const float* ln_b = (const float*)d_in[8];
    const float* Wq   = (const float*)d_in[9];
    const float* Wk   = (const float*)d_in[10];
    const float* Wv   = (const float*)d_in[11];
    const float* Wao  = (const float*)d_in[12];
    const float* Wvec = (const float*)d_in[13];
    const float* Wdv  = (const float*)d_in[14];
    const float* bdv  = (const float*)d_in[15];
    const float* Ws   = (const float*)d_in[16];
    const float* bs   = (const float*)d_in[17];
    const float* Wo   = (const float*)d_in[18];
    const float* bo   = (const float*)d_in[19];
    const float* Wf   = (const float*)d_in[20];
    const float* bf   = (const float*)d_in[21];
    const float* Wsrc = (const float*)d_in[22];
    const float* Wtrg = (const float*)d_in[23];

    const int* src = ei;
    const int* dst = ei + EE;

    float* out      = (float*)d_out;
    float* out_dx   = out;
    float* out_dvec = out + (size_t)BN * HH;
    float* out_df   = out_dvec + (size_t)BN * VD * HH;

    float *p_xn, *p_q, *p_k, *p_vv, *p_vatt, *p_v, *p_dv, *p_vp,
          *p_vj, *p_s12, *p_xagg, *p_o, *p_T, *p_S, *p_ff;
    cudaGetSymbolAddress((void**)&p_xn,   g_xn);
    cudaGetSymbolAddress((void**)&p_q,    g_q);
    cudaGetSymbolAddress((void**)&p_k,    g_k);
    cudaGetSymbolAddress((void**)&p_vv,   g_vv);
    cudaGetSymbolAddress((void**)&p_vatt, g_vatt);
    cudaGetSymbolAddress((void**)&p_v,    g_v);
    cudaGetSymbolAddress((void**)&p_dv,   g_dv);
    cudaGetSymbolAddress((void**)&p_vp,   g_vp);
    cudaGetSymbolAddress((void**)&p_vj,   g_vj);
    cudaGetSymbolAddress((void**)&p_s12,  g_s12);
    cudaGetSymbolAddress((void**)&p_xagg, g_xagg);
    cudaGetSymbolAddress((void**)&p_o,    g_o);
    cudaGetSymbolAddress((void**)&p_T,    g_T);
    cudaGetSymbolAddress((void**)&p_S,    g_S);
    cudaGetSymbolAddress((void**)&p_ff,   g_ff);

    // zero accumulators up front
    cudaMemsetAsync(p_xagg, 0, (size_t)BN * HH * sizeof(float), 0);
    cudaMemsetAsync(out_dvec, 0, (size_t)BN * VD * HH * sizeof(float), 0);

    // 1. LayerNorm
    ln_kernel<<<BN, 256>>>(x, ln_w, ln_b, p_xn);

    // 2. q/k/v fused (z=3), 64x64 tiles -> 384 CTAs
    {
        Batch3 g{};
        g.B[0] = Wq; g.B[1] = Wk; g.B[2] = Wv;
        g.C[0] = p_q; g.C[1] = p_k; g.C[2] = p_vv;
        sgemm_kernel<64, 64, false, false>
            <<<dim3(HH / 64, BN / 64, 3), 256>>>(p_xn, g, BN, HH, HH);
    }

    // 3. attention (128 CTAs x 128 thr)
    attn_kernel<<<BB * NHD * 2, 128>>>(p_q, p_k, p_vv, p_vatt);

    // 4. Wao (64x64 tiles -> 128 CTAs)
    sgemm_kernel<64, 64, false, false>
        <<<dim3(HH / 64, BN / 64, 1), 256>>>(p_vatt, one(Wao, nullptr, p_v), BN, HH, HH);

    // 5. dv/ff fused (z=2): silu(f_ij@W + b), 128x128 -> 512 CTAs
    {
        Batch3 g{};
        g.B[0] = Wdv; g.B[1] = Wf;
        g.bias[0] = bdv; g.bias[1] = bf;
        g.C[0] = p_dv; g.C[1] = p_ff;
        sgemm_kernel<128, 128, true, true>
            <<<dim3(HH / 128, EE / 128, 2), 256>>>(f_ij, g, EE, HH, HH);
    }

    // 6. v_j
    vj_kernel<<<EE, 256>>>(p_v, p_dv, src, r_ij, p_vj);

    // 7. s12 = silu(v_j@Ws + bs): 16384x512 -> 512 CTAs
    sgemm_kernel<128, 128, true, true>
        <<<dim3(2 * HH / 128, EE / 128, 1), 256>>>(p_vj, one(Ws, bs, p_s12), EE, 2 * HH, HH);

    // 8. vp = vec@Wvec: 16384x512 -> 512 CTAs
    sgemm_kernel<128, 128, false, false>
        <<<dim3(2 * HH / 128, (BN * VD) / 128, 1), 256>>>(vec, one(Wvec, nullptr, p_vp),
                                                          BN * VD, 2 * HH, HH);

    // 9. scatter-add
    scatter_kernel<<<EE, 256>>>(p_vj, p_s12, vec, d_ij, src, dst, p_xagg, out_dvec);

    // 10. o = x_agg@Wo + bo: 2048x768, 64x64 -> 384 CTAs
    sgemm_kernel<64, 64, false, true>
        <<<dim3(3 * HH / 64, BN / 64, 1), 256>>>(p_xagg, one(Wo, bo, p_o), BN, 3 * HH, HH);

    // 11. dx, dvec += vec3*o1 (vecsum folded in)
    finalize_kernel<<<BN, 256>>>(p_o, p_vp, out_dx, out_dvec);

    // 12. T/S fused (z=2): node-level hoist of per-edge GEMMs, 512 CTAs
    {
        Batch3 g{};
        g.B[0] = Wtrg; g.B[1] = Wsrc;
        g.C[0] = p_T;  g.C[1] = p_S;
        sgemm_kernel<128, 128, false, false>
            <<<dim3(HH / 128, (BN * VD) / 128, 2), 256>>>(vec, g, BN * VD, HH, HH);
    }

    // 13. w_dot + df_ij
    wdot_kernel<<<EE, 256>>>(p_T, p_S, p_ff, d_ij, src, dst, out_df);
}

// round 4
// speedup vs baseline: 2.0518x; 1.6887x over previous
#include <cuda_runtime.h>
#include <cuda_bf16.h>
#include <cstdint>

// Problem constants
#define BB 8
#define NN 256
#define BN 2048          // BB*NN
#define EE 16384
#define HH 256
#define NHD 8
#define HD 32
#define VD 8

typedef __nv_bfloat16 bf16;

// ---------------- fp32 scratch ------------------------------------------------
__device__ float g_q   [BN*HH];
__device__ float g_k   [BN*HH];
__device__ float g_vv  [BN*HH];
__device__ float g_v   [BN*HH];
__device__ float g_dv  [EE*HH];
__device__ float g_vp  [BN*VD*2*HH];
__device__ float g_s12 [EE*2*HH];
__device__ float g_xagg[BN*HH];
__device__ float g_o   [BN*3*HH];
__device__ float g_T   [BN*VD*HH];
__device__ float g_S   [BN*VD*HH];
__device__ float g_ff  [EE*HH];

// ---------------- bf16 hi/lo scratch -----------------------------------------
__device__ bf16 g_xnh [BN*HH],    g_xnl [BN*HH];
__device__ bf16 g_vath[BN*HH],    g_vatl[BN*HH];
__device__ bf16 g_fijh[EE*HH],    g_fijl[EE*HH];
__device__ bf16 g_vjh [EE*HH],    g_vjl [EE*HH];
__device__ bf16 g_vech[BN*VD*HH], g_vecl[BN*VD*HH];
__device__ bf16 g_xagh[BN*HH],    g_xagl[BN*HH];
// all weights transposed to [N][K=256] bf16, concatenated (3840 rows total)
#define WROWS 3840
__device__ bf16 g_wh[WROWS*HH], g_wl[WROWS*HH];

// weight row offsets within g_wh/g_wl
#define OFF_WQ   0
#define OFF_WK   256
#define OFF_WV   512
#define OFF_WAO  768
#define OFF_WDV  1024
#define OFF_WF   1280
#define OFF_WS   1536
#define OFF_WVEC 2048
#define OFF_WO   2560
#define OFF_WTRG 3328
#define OFF_WSRC 3584

__device__ __forceinline__ float silu_f(float x) { return x / (1.f + __expf(-x)); }

__device__ __forceinline__ uint32_t smem_u32(const void* p) {
    uint32_t a;
    asm("{ .reg .u64 t; cvta.to.shared.u64 t, %1; cvt.u32.u64 %0, t; }" : "=r"(a) : "l"(p));
    return a;
}

// ---------------- mma.sync / ldmatrix / cp.async wrappers (PTX-portable) -----
__device__ __forceinline__ void ldsm4(uint32_t* r, uint32_t addr) {
    asm volatile("ldmatrix.sync.aligned.m8n8.x4.shared.b16 {%0,%1,%2,%3}, [%4];"
                 : "=r"(r[0]), "=r"(r[1]), "=r"(r[2]), "=r"(r[3]) : "r"(addr));
}
__device__ __forceinline__ void mma_bf16(float* d, const uint32_t* a, const uint32_t* b) {
    asm volatile("mma.sync.aligned.m16n8k16.row.col.f32.bf16.bf16.f32 "
                 "{%0,%1,%2,%3}, {%4,%5,%6,%7}, {%8,%9}, {%0,%1,%2,%3};"
                 : "+f"(d[0]), "+f"(d[1]), "+f"(d[2]), "+f"(d[3])
                 : "r"(a[0]), "r"(a[1]), "r"(a[2]), "r"(a[3]), "r"(b[0]), "r"(b[1]));
}
#define CP_COMMIT() asm volatile("cp.async.commit_group;" ::: "memory")

// =============================================================================
// mma_gemm: C[128 x 128] tile of act(A @ W^T + bias).
// A: [M][256] bf16 hi/lo (K contiguous). W: [N][256] bf16 hi/lo (K contiguous).
// K in 4 chunks of 64 (128B rows, SW128 swizzle), cp.async double buffered.
// fp32 accum of Ahi*Bhi + Ahi*Blo + Alo*Bhi via mma.sync m16n8k16.
// =============================================================================
struct TcB {
    const bf16* Bh[3];
    const bf16* Bl[3];
    const float* bias[3];
    float* C[3];
};

#define MG_SMEM 131072

__device__ __forceinline__ void cp_tile(uint32_t dst_s, const bf16* __restrict__ src,
                                        int rowbase, int kc, int tid)
{
    const char* g = (const char*)(src + (size_t)rowbase * HH + kc * 64);
#pragma unroll
    for (int it = 0; it < 4; it++) {
        int u   = tid + it * 256;       // 1024 16B units: 128 rows x 8
        int row = u >> 3;
        int ui  = u & 7;
        uint32_t off = row * 128 + ui * 16;
        off ^= (off >> 3) & 0x70;
        asm volatile("cp.async.cg.shared.global [%0], [%1], 16;"
                     :: "r"(dst_s + off), "l"(g + (size_t)row * 512 + ui * 16));
    }
}

__device__ __forceinline__ void cp_chunk(uint32_t sbase,
    const bf16* Ah, const bf16* Al, const bf16* Bh, const bf16* Bl,
    int rowA, int rowB, int kc, int tid)
{
    cp_tile(sbase,         Ah, rowA, kc, tid);
    cp_tile(sbase + 16384, Al, rowA, kc, tid);
    cp_tile(sbase + 32768, Bh, rowB, kc, tid);
    cp_tile(sbase + 49152, Bl, rowB, kc, tid);
}

template<bool SILU, bool BIAS>
__global__ __launch_bounds__(256) void mma_gemm(
    const bf16* __restrict__ Ah, const bf16* __restrict__ Al, TcB gb, int Nfull)
{
    extern __shared__ uint8_t smem[];
    const int tid = threadIdx.x, wid = tid >> 5, lane = tid & 31;
    const int z = blockIdx.z;
    const bf16* __restrict__ Bh = gb.Bh[z];
    const bf16* __restrict__ Bl = gb.Bl[z];

    const int rowA = blockIdx.y * 128;
    const int rowB = blockIdx.x * 128;
    const int wr = wid >> 2, wc = wid & 3;   // warp tile: 64 rows x 32 cols

    // per-lane ldmatrix base byte offsets within a 128x128B tile
    uint32_t aoff[4], boff[2];
#pragma unroll
    for (int i = 0; i < 4; i++)
        aoff[i] = (uint32_t)((wr * 64 + i * 16 + (lane & 15)) * 128 + (lane >> 4) * 16);
    {
        int grp = lane >> 3, lr = lane & 7;
#pragma unroll
        for (int j2 = 0; j2 < 2; j2++)
            boff[j2] = (uint32_t)((wc * 32 + j2 * 16 + (grp >> 1) * 8 + lr) * 128
                                  + (grp & 1) * 16);
    }

    const uint32_t sb = smem_u32(smem);

    float acc[4][4][4];
#pragma unroll
    for (int i = 0; i < 4; i++)
#pragma unroll
        for (int j = 0; j < 4; j++)
#pragma unroll
            for (int r = 0; r < 4; r++) acc[i][j][r] = 0.f;

    // prologue: chunks 0,1 in flight
    cp_chunk(sb,         Ah, Al, Bh, Bl, rowA, rowB, 0, tid); CP_COMMIT();
    cp_chunk(sb + 65536, Ah, Al, Bh, Bl, rowA, rowB, 1, tid); CP_COMMIT();

    int buf = 0;
    for (int kc = 0; kc < 4; kc++) {
        if (kc < 3) asm volatile("cp.async.wait_group 1;" ::: "memory");
        else        asm volatile("cp.async.wait_group 0;" ::: "memory");
        __syncthreads();
        const uint32_t base = sb + buf * 65536;
#pragma unroll
        for (int ks = 0; ks < 4; ks++) {
            const uint32_t kb = ks * 32;
            uint32_t ahf[4][4], alf[4][4], bhf[2][4], blf[2][4];
#pragma unroll
            for (int i = 0; i < 4; i++) {
                uint32_t o = aoff[i] + kb; o ^= (o >> 3) & 0x70;
                ldsm4(ahf[i], base + o);
                ldsm4(alf[i], base + 16384 + o);
            }
#pragma unroll
            for (int j2 = 0; j2 < 2; j2++) {
                uint32_t o = boff[j2] + kb; o ^= (o >> 3) & 0x70;
                ldsm4(bhf[j2], base + 32768 + o);
                ldsm4(blf[j2], base + 49152 + o);
            }
#pragma unroll
            for (int i = 0; i < 4; i++)
#pragma unroll
                for (int j = 0; j < 4; j++) {
                    const uint32_t* b_hi = &bhf[j >> 1][(j & 1) * 2];
                    const uint32_t* b_lo = &blf[j >> 1][(j & 1) * 2];
                    mma_bf16(acc[i][j], ahf[i], b_hi);
                    mma_bf16(acc[i][j], ahf[i], b_lo);
                    mma_bf16(acc[i][j], alf[i], b_hi);
                }
        }
        __syncthreads();
        if (kc + 2 <= 3) {
            cp_chunk(sb + buf * 65536, Ah, Al, Bh, Bl, rowA, rowB, kc + 2, tid);
            CP_COMMIT();
        }
        buf ^= 1;
    }

    // epilogue
    float* __restrict__ C = gb.C[z];
    const float* bias = gb.bias[z];
    const int r0 = lane >> 2, c0 = (lane & 3) * 2;
#pragma unroll
    for (int i = 0; i < 4; i++) {
        const int grow = rowA + wr * 64 + i * 16 + r0;
#pragma unroll
        for (int j = 0; j < 4; j++) {
            const int gcol = rowB + wc * 32 + j * 8 + c0;
            float v0 = acc[i][j][0], v1 = acc[i][j][1];
            float v2 = acc[i][j][2], v3 = acc[i][j][3];
            if (BIAS) {
                float b0 = bias[gcol], b1 = bias[gcol + 1];
                v0 += b0; v1 += b1; v2 += b0; v3 += b1;
            }
            if (SILU) { v0 = silu_f(v0); v1 = silu_f(v1); v2 = silu_f(v2); v3 = silu_f(v3); }
            *(float2*)(C + (size_t)grow * Nfull + gcol)       = make_float2(v0, v1);
            *(float2*)(C + (size_t)(grow + 8) * Nfull + gcol) = make_float2(v2, v3);
        }
    }
}

static TcB one(const bf16* bh, const bf16* bl, const float* bias, float* C) {
    TcB g{};
    g.Bh[0] = bh; g.Bl[0] = bl; g.bias[0] = bias; g.C[0] = C;
    return g;
}

// ======================= weight prep: W[K][N] -> [N][K] hi/lo ================
struct WPrep {
    const float* src[11];
    int N[11];
    int off[11];
};
__global__ __launch_bounds__(256) void wprep_kernel(WPrep wp, bf16* wh, bf16* wl)
{
    int w = blockIdx.y;
    int n = blockIdx.x;
    int Nw = wp.N[w];
    if (n >= Nw) return;
    int k = threadIdx.x;
    float v = wp.src[w][(size_t)k * Nw + n];
    bf16 h = __float2bfloat16(v);
    bf16 l = __float2bfloat16(v - __bfloat162float(h));
    size_t o = (size_t)(wp.off[w] + n) * HH + k;
    wh[o] = h; wl[o] = l;
}

// ======================= fp32 -> bf16 hi/lo convert ==========================
__global__ __launch_bounds__(256) void conv_kernel(const float* __restrict__ in,
                                                   bf16* __restrict__ hi,
                                                   bf16* __restrict__ lo, int n4)
{
    int i = blockIdx.x * 256 + threadIdx.x;
    if (i >= n4) return;
    float4 v = ((const float4*)in)[i];
    bf16 h0 = __float2bfloat16(v.x), h1 = __float2bfloat16(v.y);
    bf16 h2 = __float2bfloat16(v.z), h3 = __float2bfloat16(v.w);
    bf16 l0 = __float2bfloat16(v.x - __bfloat162float(h0));
    bf16 l1 = __float2bfloat16(v.y - __bfloat162float(h1));
    bf16 l2 = __float2bfloat16(v.z - __bfloat162float(h2));
    bf16 l3 = __float2bfloat16(v.w - __bfloat162float(h3));
    __nv_bfloat162* hp = (__nv_bfloat162*)hi;
    __nv_bfloat162* lp = (__nv_bfloat162*)lo;
    hp[2 * i]     = __nv_bfloat162(h0, h1);
    hp[2 * i + 1] = __nv_bfloat162(h2, h3);
    lp[2 * i]     = __nv_bfloat162(l0, l1);
    lp[2 * i + 1] = __nv_bfloat162(l2, l3);
}

// ======================= LayerNorm -> bf16 hi/lo =============================
__global__ __launch_bounds__(256) void ln_kernel(const float* __restrict__ x,
                                                 const float* __restrict__ w,
                                                 const float* __restrict__ b,
                                                 bf16* __restrict__ xh,
                                                 bf16* __restrict__ xl)
{
    int n = blockIdx.x, h = threadIdx.x;
    __shared__ float red[8];
    float v = x[n * HH + h];
    float s = v;
#pragma unroll
    for (int o = 16; o; o >>= 1) s += __shfl_xor_sync(0xffffffffu, s, o);
    if ((h & 31) == 0) red[h >> 5] = s;
    __syncthreads();
    float tot = 0.f;
#pragma unroll
    for (int i = 0; i < 8; i++) tot += red[i];
    float mu = tot * (1.f / HH);
    float dv = v - mu;
    float s2 = dv * dv;
#pragma unroll
    for (int o = 16; o; o >>= 1) s2 += __shfl_xor_sync(0xffffffffu, s2, o);
    __syncthreads();
    if ((h & 31) == 0) red[h >> 5] = s2;
    __syncthreads();
    float var = 0.f;
#pragma unroll
    for (int i = 0; i < 8; i++) var += red[i];
    var *= (1.f / HH);
    float xn = dv * rsqrtf(var + 1e-5f) * w[h] + b[h];
    bf16 hh2 = __float2bfloat16(xn);
    xh[n * HH + h] = hh2;
    xl[n * HH + h] = __float2bfloat16(xn - __bfloat162float(hh2));
}

// ======================= attention -> bf16 hi/lo =============================
__global__ __launch_bounds__(128) void attn_kernel(const float* __restrict__ q,
                                                   const float* __restrict__ k,
                                                   const float* __restrict__ vv,
                                                   bf16* __restrict__ oh,
                                                   bf16* __restrict__ ol)
{
    int blk = blockIdx.x;
    int b = blk >> 4;
    int hd = (blk >> 1) & 7;
    int i = (blk & 1) * 128 + threadIdx.x;
    __shared__ float ks[64][32];
    __shared__ float vs[64][32];
    float qr[32];
    const float* qrow = q + (size_t)(b * NN + i) * HH + hd * HD;
#pragma unroll
    for (int d = 0; d < 32; d++) qr[d] = qrow[d];
    float acc[32];
#pragma unroll
    for (int d = 0; d < 32; d++) acc[d] = 0.f;
    const float scale = rsqrtf((float)HD);

    for (int j0 = 0; j0 < NN; j0 += 64) {
        __syncthreads();
        for (int l = threadIdx.x; l < 512; l += 128) {
            int jr = l >> 3;
            int dc = (l & 7) * 4;
            size_t base = (size_t)(b * NN + j0 + jr) * HH + hd * HD + dc;
            *(float4*)&ks[jr][dc] = *(const float4*)&k[base];
            *(float4*)&vs[jr][dc] = *(const float4*)&vv[base];
        }
        __syncthreads();
        for (int j = 0; j < 64; j++) {
            float s = 0.f;
#pragma unroll
            for (int d = 0; d < 32; d++) s += qr[d] * ks[j][d];
            s = silu_f(s * scale);
#pragma unroll
            for (int d = 0; d < 32; d++) acc[d] += s * vs[j][d];
        }
    }
    size_t base = (size_t)(b * NN + i) * HH + hd * HD;
#pragma unroll
    for (int d = 0; d < 32; d++) {
        float val = acc[d] * (1.f / NN);
        bf16 h2 = __float2bfloat16(val);
        oh[base + d] = h2;
        ol[base + d] = __float2bfloat16(val - __bfloat162float(h2));
    }
}

// ======================= v_j -> bf16 hi/lo ===================================
__global__ __launch_bounds__(256) void vj_kernel(const float* __restrict__ v,
                                                 const float* __restrict__ dv,
                                                 const int* __restrict__ src,
                                                 const float* __restrict__ r,
                                                 bf16* __restrict__ vjh,
                                                 bf16* __restrict__ vjl)
{
    int e = blockIdx.x, h = threadIdx.x;
    float rr = r[e];
    float cut = (rr < 5.f) ? 0.5f * (cosf(rr * 0.6283185307179586f) + 1.f) : 0.f;
    float val = v[(size_t)src[e] * HH + h] * cut * dv[(size_t)e * HH + h];
    bf16 h2 = __float2bfloat16(val);
    vjh[(size_t)e * HH + h] = h2;
    vjl[(size_t)e * HH + h] = __float2bfloat16(val - __bfloat162float(h2));
}

// ======================= scatter: x_agg += v_j ; dvec += vec_j ===============
__global__ __launch_bounds__(256) void scatter_kernel(const bf16* __restrict__ vjh,
                                                      const bf16* __restrict__ vjl,
                                                      const float* __restrict__ s12,
                                                      const float* __restrict__ vec,
                                                      const float* __restrict__ dij,
                                                      const int* __restrict__ src,
                                                      const int* __restrict__ dst,
                                                      float* __restrict__ xagg,
                                                      float* __restrict__ dvec_out)
{
    int e = blockIdx.x, h = threadIdx.x;
    __shared__ float dsh[VD];
    if (h < VD) dsh[h] = dij[e * VD + h];
    __syncthreads();
    int s = src[e], t = dst[e];
    float vje = __bfloat162float(vjh[(size_t)e * HH + h]) +
                __bfloat162float(vjl[(size_t)e * HH + h]);
    atomicAdd(&xagg[(size_t)t * HH + h], vje);
    float s1  = s12[(size_t)e * (2 * HH) + h];
    float s2v = s12[(size_t)e * (2 * HH) + HH + h];
#pragma unroll
    for (int vd = 0; vd < VD; vd++) {
        float val = vec[(size_t)s * (VD * HH) + vd * HH + h] * s1 + s2v * dsh[vd];
        atomicAdd(&dvec_out[(size_t)t * (VD * HH) + vd * HH + h], val);
    }
}

// ======================= finalize ============================================
__global__ __launch_bounds__(256) void finalize_kernel(const float* __restrict__ o,
                                                       const float* __restrict__ vp,
                                                       float* __restrict__ dx,
                                                       float* __restrict__ dvec)
{
    int n = blockIdx.x, h = threadIdx.x;
    float o1 = o[(size_t)n * (3 * HH) + h];
    float o2 = o[(size_t)n * (3 * HH) + HH + h];
    float o3 = o[(size_t)n * (3 * HH) + 2 * HH + h];
    float vsum = 0.f;
#pragma unroll
    for (int vd = 0; vd < VD; vd++)
        vsum += vp[(size_t)(n * VD + vd) * (2 * HH) + h];
    dx[n * HH + h] = vsum * o2 + o3;
#pragma unroll
    for (int vd = 0; vd < VD; vd++) {
        float vec3 = vp[(size_t)(n * VD + vd) * (2 * HH) + HH + h];
        dvec[(size_t)n * (VD * HH) + vd * HH + h] += vec3 * o1;
    }
}

// ======================= w_dot + df_ij =======================================
__global__ __launch_bounds__(256) void wdot_kernel(const float* __restrict__ T,
                                                   const float* __restrict__ S,
                                                   const float* __restrict__ ff,
                                                   const float* __restrict__ dij,
                                                   const int* __restrict__ src,
                                                   const int* __restrict__ dst,
                                                   float* __restrict__ df)
{
    int e = blockIdx.x, h = threadIdx.x;
    __shared__ float dsh[VD];
    if (h < VD) dsh[h] = dij[e * VD + h];
    __syncthreads();
    int s = src[e], t = dst[e];
    float tv[VD], sv[VD];
    float pT = 0.f, pS = 0.f;
#pragma unroll
    for (int vd = 0; vd < VD; vd++) {
        tv[vd] = T[(size_t)(t * VD + vd) * HH + h];
        sv[vd] = S[(size_t)(s * VD + vd) * HH + h];
        pT += tv[vd] * dsh[vd];
        pS += sv[vd] * dsh[vd];
    }
    float wd = 0.f;
#pragma unroll
    for (int vd = 0; vd < VD; vd++)
        wd += (tv[vd] - pT * dsh[vd]) * (sv[vd] - pS * dsh[vd]);
    df[(size_t)e * HH + h] = ff[(size_t)e * HH + h] * wd;
}

// ======================= launcher ============================================
extern "C" void kernel_launch(void* const* d_in, const int* in_sizes, int n_in,
                              void* d_out, int out_size)
{
    const float* x    = (const float*)d_in[0];
    const float* vec  = (const float*)d_in[1];
    const int*   ei   = (const int*)d_in[2];
    const float* r_ij = (const float*)d_in[3];
    const float* f_ij = (const float*)d_in[4];
    const float* d_ij = (const float*)d_in[5];
    const float* ln_w = (const float*)d_in[7];
    const float* ln_b = (const float*)d_in[8];
    const float* Wq   = (const float*)d_in[9];
    const float* Wk   = (const float*)d_in[10];
    const float* Wv   = (const float*)d_in[11];
    const float* Wao  = (const float*)d_in[12];
    const float* Wvec = (const float*)d_in[13];
    const float* Wdv  = (const float*)d_in[14];
    const float* bdv  = (const float*)d_in[15];
    const float* Ws   = (const float*)d_in[16];
    const float* bs   = (const float*)d_in[17];
    const float* Wo   = (const float*)d_in[18];
    const float* bo   = (const float*)d_in[19];
    const float* Wf   = (const float*)d_in[20];
    const float* bf   = (const float*)d_in[21];
    const float* Wsrc = (const float*)d_in[22];
    const float* Wtrg = (const float*)d_in[23];

    const int* src = ei;
    const int* dst = ei + EE;

    float* out      = (float*)d_out;
    float* out_dx   = out;
    float* out_dvec = out + (size_t)BN * HH;
    float* out_df   = out_dvec + (size_t)BN * VD * HH;

    float *p_q, *p_k, *p_vv, *p_v, *p_dv, *p_vp, *p_s12, *p_xagg, *p_o, *p_T, *p_S, *p_ff;
    bf16 *p_xnh, *p_xnl, *p_vath, *p_vatl, *p_fijh, *p_fijl, *p_vjh, *p_vjl,
         *p_vech, *p_vecl, *p_xagh, *p_xagl, *p_wh, *p_wl;
    cudaGetSymbolAddress((void**)&p_q,    g_q);
    cudaGetSymbolAddress((void**)&p_k,    g_k);
    cudaGetSymbolAddress((void**)&p_vv,   g_vv);
    cudaGetSymbolAddress((void**)&p_v,    g_v);
    cudaGetSymbolAddress((void**)&p_dv,   g_dv);
    cudaGetSymbolAddress((void**)&p_vp,   g_vp);
    cudaGetSymbolAddress((void**)&p_s12,  g_s12);
    cudaGetSymbolAddress((void**)&p_xagg, g_xagg);
    cudaGetSymbolAddress((void**)&p_o,    g_o);
    cudaGetSymbolAddress((void**)&p_T,    g_T);
    cudaGetSymbolAddress((void**)&p_S,    g_S);
    cudaGetSymbolAddress((void**)&p_ff,   g_ff);
    cudaGetSymbolAddress((void**)&p_xnh,  g_xnh);
    cudaGetSymbolAddress((void**)&p_xnl,  g_xnl);
    cudaGetSymbolAddress((void**)&p_vath, g_vath);
    cudaGetSymbolAddress((void**)&p_vatl, g_vatl);
    cudaGetSymbolAddress((void**)&p_fijh, g_fijh);
    cudaGetSymbolAddress((void**)&p_fijl, g_fijl);
    cudaGetSymbolAddress((void**)&p_vjh,  g_vjh);
    cudaGetSymbolAddress((void**)&p_vjl,  g_vjl);
    cudaGetSymbolAddress((void**)&p_vech, g_vech);
    cudaGetSymbolAddress((void**)&p_vecl, g_vecl);
    cudaGetSymbolAddress((void**)&p_xagh, g_xagh);
    cudaGetSymbolAddress((void**)&p_xagl, g_xagl);
    cudaGetSymbolAddress((void**)&p_wh,   g_wh);
    cudaGetSymbolAddress((void**)&p_wl,   g_wl);

    cudaFuncSetAttribute(mma_gemm<false, false>, cudaFuncAttributeMaxDynamicSharedMemorySize, MG_SMEM);
    cudaFuncSetAttribute(mma_gemm<true,  true >, cudaFuncAttributeMaxDynamicSharedMemorySize, MG_SMEM);
    cudaFuncSetAttribute(mma_gemm<false, true >, cudaFuncAttributeMaxDynamicSharedMemorySize, MG_SMEM);

    // zero accumulators
    cudaMemsetAsync(p_xagg, 0, (size_t)BN * HH * sizeof(float), 0);
    cudaMemsetAsync(out_dvec, 0, (size_t)BN * VD * HH * sizeof(float), 0);

    // weight prep (all 11 weights -> [N][K] bf16 hi/lo)
    {
        WPrep wp{};
        const float* srcs[11] = {Wq, Wk, Wv, Wao, Wdv, Wf, Ws, Wvec, Wo, Wtrg, Wsrc};
        int ns[11]   = {256, 256, 256, 256, 256, 256, 512, 512, 768, 256, 256};
        int offs[11] = {OFF_WQ, OFF_WK, OFF_WV, OFF_WAO, OFF_WDV, OFF_WF,
                        OFF_WS, OFF_WVEC, OFF_WO, OFF_WTRG, OFF_WSRC};
        for (int i = 0; i < 11; i++) { wp.src[i] = srcs[i]; wp.N[i] = ns[i]; wp.off[i] = offs[i]; }
        wprep_kernel<<<dim3(768, 11), 256>>>(wp, p_wh, p_wl);
    }

    // input converts
    conv_kernel<<<(EE * HH / 4 + 255) / 256, 256>>>(f_ij, p_fijh, p_fijl, EE * HH / 4);
    conv_kernel<<<(BN * VD * HH / 4 + 255) / 256, 256>>>(vec, p_vech, p_vecl, BN * VD * HH / 4);

    // 1. LayerNorm -> bf16 hi/lo
    ln_kernel<<<BN, 256>>>(x, ln_w, ln_b, p_xnh, p_xnl);

    // 2. q/k/v (z=3)
    {
        TcB g{};
        g.Bh[0] = p_wh + (size_t)OFF_WQ * HH; g.Bl[0] = p_wl + (size_t)OFF_WQ * HH; g.C[0] = p_q;
        g.Bh[1] = p_wh + (size_t)OFF_WK * HH; g.Bl[1] = p_wl + (size_t)OFF_WK * HH; g.C[1] = p_k;
        g.Bh[2] = p_wh + (size_t)OFF_WV * HH; g.Bl[2] = p_wl + (size_t)OFF_WV * HH; g.C[2] = p_vv;
        mma_gemm<false, false><<<dim3(2, 16, 3), 256, MG_SMEM>>>(p_xnh, p_xnl, g, HH);
    }

    // 3. attention -> vatt bf16 hi/lo
    attn_kernel<<<BB * NHD * 2, 128>>>(p_q, p_k, p_vv, p_vath, p_vatl);

    // 4. v = vatt @ Wao
    mma_gemm<false, false><<<dim3(2, 16, 1), 256, MG_SMEM>>>(
        p_vath, p_vatl, one(p_wh + (size_t)OFF_WAO * HH, p_wl + (size_t)OFF_WAO * HH, nullptr, p_v), HH);

    // 5. dv/ff fused (z=2): silu(f_ij @ W + b)
    {
        TcB g{};
        g.Bh[0] = p_wh + (size_t)OFF_WDV * HH; g.Bl[0] = p_wl + (size_t)OFF_WDV * HH;
        g.bias[0] = bdv; g.C[0] = p_dv;
        g.Bh[1] = p_wh + (size_t)OFF_WF * HH;  g.Bl[1] = p_wl + (size_t)OFF_WF * HH;
        g.bias[1] = bf;  g.C[1] = p_ff;
        mma_gemm<true, true><<<dim3(2, 128, 2), 256, MG_SMEM>>>(p_fijh, p_fijl, g, HH);
    }

    // 6. v_j -> bf16 hi/lo
    vj_kernel<<<EE, 256>>>(p_v, p_dv, src, r_ij, p_vjh, p_vjl);

    // 7. s12 = silu(v_j @ Ws + bs)   N=512
    mma_gemm<true, true><<<dim3(4, 128, 1), 256, MG_SMEM>>>(
        p_vjh, p_vjl, one(p_wh + (size_t)OFF_WS * HH, p_wl + (size_t)OFF_WS * HH, bs, p_s12), 2 * HH);

    // 8. vp = vec @ Wvec   N=512
    mma_gemm<false, false><<<dim3(4, 128, 1), 256, MG_SMEM>>>(
        p_vech, p_vecl, one(p_wh + (size_t)OFF_WVEC * HH, p_wl + (size_t)OFF_WVEC * HH, nullptr, p_vp), 2 * HH);

    // 9. scatter-add
    scatter_kernel<<<EE, 256>>>(p_vjh, p_vjl, p_s12, vec, d_ij, src, dst, p_xagg, out_dvec);

    // 10. xagg -> bf16 hi/lo, then o = x_agg @ Wo + bo  (N=768)
    conv_kernel<<<(BN * HH / 4 + 255) / 256, 256>>>(p_xagg, p_xagh, p_xagl, BN * HH / 4);
    mma_gemm<false, true><<<dim3(6, 16, 1), 256, MG_SMEM>>>(
        p_xagh, p_xagl, one(p_wh + (size_t)OFF_WO * HH, p_wl + (size_t)OFF_WO * HH, bo, p_o), 3 * HH);

    // 11. finalize
    finalize_kernel<<<BN, 256>>>(p_o, p_vp, out_dx, out_dvec);

    // 12. T/S fused (z=2)
    {
        TcB g{};
        g.Bh[0] = p_wh + (size_t)OFF_WTRG * HH; g.Bl[0] = p_wl + (size_t)OFF_WTRG * HH; g.C[0] = p_T;
        g.Bh[1] = p_wh + (size_t)OFF_WSRC * HH; g.Bl[1] = p_wl + (size_t)OFF_WSRC * HH; g.C[1] = p_S;
        mma_gemm<false, false><<<dim3(2, 128, 2), 256, MG_SMEM>>>(p_vech, p_vecl, g, HH);
    }

    // 13. w_dot + df_ij
    wdot_kernel<<<EE, 256>>>(p_T, p_S, p_ff, d_ij, src, dst, out_df);
}

// round 5
// speedup vs baseline: 2.0615x; 1.0047x over previous
#include <cuda_runtime.h>
#include <cuda_bf16.h>
#include <cstdint>

// Problem constants
#define BB 8
#define NN 256
#define BN 2048          // BB*NN
#define EE 16384
#define HH 256
#define NHD 8
#define HD 32
#define VD 8

typedef __nv_bfloat16 bf16;

// ---------------- fp32 scratch ------------------------------------------------
__device__ float g_q   [BN*HH];
__device__ float g_k   [BN*HH];
__device__ float g_vv  [BN*HH];
__device__ float g_v   [BN*HH];
__device__ float g_vp  [BN*VD*2*HH];
__device__ float g_s12 [EE*2*HH];
__device__ float g_o   [BN*3*HH];
__device__ float g_T   [BN*VD*HH];
__device__ float g_S   [BN*VD*HH];
__device__ float g_ff  [EE*HH];

// ---------------- bf16 hi/lo scratch -----------------------------------------
__device__ bf16 g_xnh [BN*HH],    g_xnl [BN*HH];
__device__ bf16 g_vath[BN*HH],    g_vatl[BN*HH];
__device__ bf16 g_fijh[EE*HH],    g_fijl[EE*HH];
__device__ bf16 g_vjh [EE*HH],    g_vjl [EE*HH];
__device__ bf16 g_vech[BN*VD*HH], g_vecl[BN*VD*HH];
__device__ bf16 g_xagh[BN*HH],    g_xagl[BN*HH];
// all weights transposed to [N][K=256] bf16, concatenated (3840 rows total)
#define WROWS 3840
__device__ bf16 g_wh[WROWS*HH], g_wl[WROWS*HH];

// ---------------- CSR scratch -------------------------------------------------
__device__ int g_cnt[BN];
__device__ int g_ofs[BN];
__device__ int g_rowstart[BN + 1];
__device__ int g_elist[EE];

// weight row offsets within g_wh/g_wl
#define OFF_WQ   0
#define OFF_WK   256
#define OFF_WV   512
#define OFF_WAO  768
#define OFF_WDV  1024
#define OFF_WF   1280
#define OFF_WS   1536
#define OFF_WVEC 2048
#define OFF_WO   2560
#define OFF_WTRG 3328
#define OFF_WSRC 3584

__device__ __forceinline__ float silu_f(float x) { return x / (1.f + __expf(-x)); }
__device__ __forceinline__ float cut_f(float rr) {
    return (rr < 5.f) ? 0.5f * (cosf(rr * 0.6283185307179586f) + 1.f) : 0.f;
}

__device__ __forceinline__ uint32_t smem_u32(const void* p) {
    uint32_t a;
    asm("{ .reg .u64 t; cvta.to.shared.u64 t, %1; cvt.u32.u64 %0, t; }" : "=r"(a) : "l"(p));
    return a;
}

// ---------------- mma.sync / ldmatrix / cp.async wrappers --------------------
__device__ __forceinline__ void ldsm4(uint32_t* r, uint32_t addr) {
    asm volatile("ldmatrix.sync.aligned.m8n8.x4.shared.b16 {%0,%1,%2,%3}, [%4];"
                 : "=r"(r[0]), "=r"(r[1]), "=r"(r[2]), "=r"(r[3]) : "r"(addr));
}
__device__ __forceinline__ void mma_bf16(float* d, const uint32_t* a, const uint32_t* b) {
    asm volatile("mma.sync.aligned.m16n8k16.row.col.f32.bf16.bf16.f32 "
                 "{%0,%1,%2,%3}, {%4,%5,%6,%7}, {%8,%9}, {%0,%1,%2,%3};"
                 : "+f"(d[0]), "+f"(d[1]), "+f"(d[2]), "+f"(d[3])
                 : "r"(a[0]), "r"(a[1]), "r"(a[2]), "r"(a[3]), "r"(b[0]), "r"(b[1]));
}
#define CP_COMMIT() asm volatile("cp.async.commit_group;" ::: "memory")

// =============================================================================
// mma_gemm: C[128 x 128] tile of epilogue(A @ W^T).
// MODE 0: plain fp32.  MODE 1: +bias fp32.  MODE 2: silu(+bias) fp32.
// MODE 3: vj epilogue: silu(acc+bias)*cut(r[row])*v[src[row]][col] -> bf16 hi/lo.
// =============================================================================
struct TcB {
    const bf16* Bh[3];
    const bf16* Bl[3];
    const float* bias[3];
    float* C[3];
};

#define MG_SMEM 131072

__device__ __forceinline__ void cp_tile(uint32_t dst_s, const bf16* __restrict__ src,
                                        int rowbase, int kc, int tid)
{
    const char* g = (const char*)(src + (size_t)rowbase * HH + kc * 64);
#pragma unroll
    for (int it = 0; it < 4; it++) {
        int u   = tid + it * 256;       // 1024 16B units: 128 rows x 8
        int row = u >> 3;
        int ui  = u & 7;
        uint32_t off = row * 128 + ui * 16;
        off ^= (off >> 3) & 0x70;
        asm volatile("cp.async.cg.shared.global [%0], [%1], 16;"
                     :: "r"(dst_s + off), "l"(g + (size_t)row * 512 + ui * 16));
    }
}

__device__ __forceinline__ void cp_chunk(uint32_t sbase,
    const bf16* Ah, const bf16* Al, const bf16* Bh, const bf16* Bl,
    int rowA, int rowB, int kc, int tid)
{
    cp_tile(sbase,         Ah, rowA, kc, tid);
    cp_tile(sbase + 16384, Al, rowA, kc, tid);
    cp_tile(sbase + 32768, Bh, rowB, kc, tid);
    cp_tile(sbase + 49152, Bl, rowB, kc, tid);
}

template<int MODE>
__global__ __launch_bounds__(256) void mma_gemm(
    const bf16* __restrict__ Ah, const bf16* __restrict__ Al, TcB gb, int Nfull,
    const float* __restrict__ vsrc, const int* __restrict__ srcidx,
    const float* __restrict__ rij, bf16* __restrict__ Oh, bf16* __restrict__ Ol)
{
    extern __shared__ uint8_t smem[];
    const int tid = threadIdx.x, wid = tid >> 5, lane = tid & 31;
    const int z = blockIdx.z;
    const bf16* __restrict__ Bh = gb.Bh[z];
    const bf16* __restrict__ Bl = gb.Bl[z];

    const int rowA = blockIdx.y * 128;
    const int rowB = blockIdx.x * 128;
    const int wr = wid >> 2, wc = wid & 3;   // warp tile: 64 rows x 32 cols

    uint32_t aoff[4], boff[2];
#pragma unroll
    for (int i = 0; i < 4; i++)
        aoff[i] = (uint32_t)((wr * 64 + i * 16 + (lane & 15)) * 128 + (lane >> 4) * 16);
    {
        int grp = lane >> 3, lr = lane & 7;
#pragma unroll
        for (int j2 = 0; j2 < 2; j2++)
            boff[j2] = (uint32_t)((wc * 32 + j2 * 16 + (grp >> 1) * 8 + lr) * 128
                                  + (grp & 1) * 16);
    }

    const uint32_t sb = smem_u32(smem);

    float acc[4][4][4];
#pragma unroll
    for (int i = 0; i < 4; i++)
#pragma unroll
        for (int j = 0; j < 4; j++)
#pragma unroll
            for (int r = 0; r < 4; r++) acc[i][j][r] = 0.f;

    cp_chunk(sb,         Ah, Al, Bh, Bl, rowA, rowB, 0, tid); CP_COMMIT();
    cp_chunk(sb + 65536, Ah, Al, Bh, Bl, rowA, rowB, 1, tid); CP_COMMIT();

    int buf = 0;
    for (int kc = 0; kc < 4; kc++) {
        if (kc < 3) asm volatile("cp.async.wait_group 1;" ::: "memory");
        else        asm volatile("cp.async.wait_group 0;" ::: "memory");
        __syncthreads();
        const uint32_t base = sb + buf * 65536;
#pragma unroll
        for (int ks = 0; ks < 4; ks++) {
            const uint32_t kb = ks * 32;
            uint32_t ahf[4][4], alf[4][4], bhf[2][4], blf[2][4];
#pragma unroll
            for (int i = 0; i < 4; i++) {
                uint32_t o = aoff[i] + kb; o ^= (o >> 3) & 0x70;
                ldsm4(ahf[i], base + o);
                ldsm4(alf[i], base + 16384 + o);
            }
#pragma unroll
            for (int j2 = 0; j2 < 2; j2++) {
                uint32_t o = boff[j2] + kb; o ^= (o >> 3) & 0x70;
                ldsm4(bhf[j2], base + 32768 + o);
                ldsm4(blf[j2], base + 49152 + o);
            }
#pragma unroll
            for (int i = 0; i < 4; i++)
#pragma unroll
                for (int j = 0; j < 4; j++) {
                    const uint32_t* b_hi = &bhf[j >> 1][(j & 1) * 2];
                    const uint32_t* b_lo = &blf[j >> 1][(j & 1) * 2];
                    mma_bf16(acc[i][j], ahf[i], b_hi);
                    mma_bf16(acc[i][j], ahf[i], b_lo);
                    mma_bf16(acc[i][j], alf[i], b_hi);
                }
        }
        __syncthreads();
        if (kc + 2 <= 3) {
            cp_chunk(sb + buf * 65536, Ah, Al, Bh, Bl, rowA, rowB, kc + 2, tid);
            CP_COMMIT();
        }
        buf ^= 1;
    }

    const float* bias = gb.bias[z];
    const int r0 = lane >> 2, c0 = (lane & 3) * 2;

    if constexpr (MODE == 3) {
        __nv_bfloat162* OH = (__nv_bfloat162*)Oh;
        __nv_bfloat162* OL = (__nv_bfloat162*)Ol;
#pragma unroll
        for (int i = 0; i < 4; i++) {
            const int row0 = rowA + wr * 64 + i * 16 + r0;
            const int row1 = row0 + 8;
            const int s0 = srcidx[row0], s1i = srcidx[row1];
            const float cut0 = cut_f(rij[row0]);
            const float cut1 = cut_f(rij[row1]);
#pragma unroll
            for (int j = 0; j < 4; j++) {
                const int gcol = rowB + wc * 32 + j * 8 + c0;
                const float b0 = bias[gcol], b1 = bias[gcol + 1];
                float v0 = silu_f(acc[i][j][0] + b0) * cut0 * vsrc[(size_t)s0 * HH + gcol];
                float v1 = silu_f(acc[i][j][1] + b1) * cut0 * vsrc[(size_t)s0 * HH + gcol + 1];
                float v2 = silu_f(acc[i][j][2] + b0) * cut1 * vsrc[(size_t)s1i * HH + gcol];
                float v3 = silu_f(acc[i][j][3] + b1) * cut1 * vsrc[(size_t)s1i * HH + gcol + 1];
                bf16 h0 = __float2bfloat16(v0), h1 = __float2bfloat16(v1);
                bf16 h2 = __float2bfloat16(v2), h3 = __float2bfloat16(v3);
                bf16 l0 = __float2bfloat16(v0 - __bfloat162float(h0));
                bf16 l1 = __float2bfloat16(v1 - __bfloat162float(h1));
                bf16 l2 = __float2bfloat16(v2 - __bfloat162float(h2));
                bf16 l3 = __float2bfloat16(v3 - __bfloat162float(h3));
                OH[(size_t)row0 * 128 + (gcol >> 1)] = __nv_bfloat162(h0, h1);
                OL[(size_t)row0 * 128 + (gcol >> 1)] = __nv_bfloat162(l0, l1);
                OH[(size_t)row1 * 128 + (gcol >> 1)] = __nv_bfloat162(h2, h3);
                OL[(size_t)row1 * 128 + (gcol >> 1)] = __nv_bfloat162(l2, l3);
            }
        }
    } else {
        float* __restrict__ C = gb.C[z];
#pragma unroll
        for (int i = 0; i < 4; i++) {
            const int grow = rowA + wr * 64 + i * 16 + r0;
#pragma unroll
            for (int j = 0; j < 4; j++) {
                const int gcol = rowB + wc * 32 + j * 8 + c0;
                float v0 = acc[i][j][0], v1 = acc[i][j][1];
                float v2 = acc[i][j][2], v3 = acc[i][j][3];
                if (MODE >= 1) {
                    float b0 = bias[gcol], b1 = bias[gcol + 1];
                    v0 += b0; v1 += b1; v2 += b0; v3 += b1;
                }
                if (MODE == 2) {
                    v0 = silu_f(v0); v1 = silu_f(v1); v2 = silu_f(v2); v3 = silu_f(v3);
                }
                *(float2*)(C + (size_t)grow * Nfull + gcol)       = make_float2(v0, v1);
                *(float2*)(C + (size_t)(grow + 8) * Nfull + gcol) = make_float2(v2, v3);
            }
        }
    }
}

// ======================= weight prep: W[K][N] -> [N][K] hi/lo ================
struct WPrep {
    const float* src[11];
    int N[11];
    int off[11];
};
__global__ __launch_bounds__(256) void wprep_kernel(WPrep wp, bf16* wh, bf16* wl)
{
    int w = blockIdx.y;
    int n = blockIdx.x;
    int Nw = wp.N[w];
    if (n >= Nw) return;
    int k = threadIdx.x;
    float v = wp.src[w][(size_t)k * Nw + n];
    bf16 h = __float2bfloat16(v);
    bf16 l = __float2bfloat16(v - __bfloat162float(h));
    size_t o = (size_t)(wp.off[w] + n) * HH + k;
    wh[o] = h; wl[o] = l;
}

// ======================= fp32 -> bf16 hi/lo convert ==========================
__global__ __launch_bounds__(256) void conv_kernel(const float* __restrict__ in,
                                                   bf16* __restrict__ hi,
                                                   bf16* __restrict__ lo, int n4)
{
    int i = blockIdx.x * 256 + threadIdx.x;
    if (i >= n4) return;
    float4 v = ((const float4*)in)[i];
    bf16 h0 = __float2bfloat16(v.x), h1 = __float2bfloat16(v.y);
    bf16 h2 = __float2bfloat16(v.z), h3 = __float2bfloat16(v.w);
    bf16 l0 = __float2bfloat16(v.x - __bfloat162float(h0));
    bf16 l1 = __float2bfloat16(v.y - __bfloat162float(h1));
    bf16 l2 = __float2bfloat16(v.z - __bfloat162float(h2));
    bf16 l3 = __float2bfloat16(v.w - __bfloat162float(h3));
    __nv_bfloat162* hp = (__nv_bfloat162*)hi;
    __nv_bfloat162* lp = (__nv_bfloat162*)lo;
    hp[2 * i]     = __nv_bfloat162(h0, h1);
    hp[2 * i + 1] = __nv_bfloat162(h2, h3);
    lp[2 * i]     = __nv_bfloat162(l0, l1);
    lp[2 * i + 1] = __nv_bfloat162(l2, l3);
}

// ======================= CSR build ===========================================
__global__ __launch_bounds__(256) void hist_kernel(const int* __restrict__ dst, int* cnt)
{
    int e = blockIdx.x * 256 + threadIdx.x;
    if (e < EE) atomicAdd(&cnt[dst[e]], 1);
}

__global__ __launch_bounds__(1024) void scan_kernel(const int* __restrict__ cnt,
                                                    int* rowstart, int* ofs)
{
    __shared__ int s[BN];
    int t = threadIdx.x;
    s[t] = cnt[t]; s[t + 1024] = cnt[t + 1024];
    __syncthreads();
#pragma unroll
    for (int d = 1; d < BN; d <<= 1) {
        int idx = (t + 1) * 2 * d - 1;
        int val = 0;
        if (idx < BN) val = s[idx - d];
        __syncthreads();
        if (idx < BN) s[idx] += val;
        __syncthreads();
    }
    if (t == 0) { rowstart[BN] = s[BN - 1]; s[BN - 1] = 0; }
    __syncthreads();
#pragma unroll
    for (int d = BN / 2; d >= 1; d >>= 1) {
        int idx = (t + 1) * 2 * d - 1;
        int a = 0, b2 = 0;
        if (idx < BN) { a = s[idx - d]; b2 = s[idx]; }
        __syncthreads();
        if (idx < BN) { s[idx - d] = b2; s[idx] = a + b2; }
        __syncthreads();
    }
    rowstart[t] = s[t]; rowstart[t + 1024] = s[t + 1024];
    ofs[t] = s[t];      ofs[t + 1024] = s[t + 1024];
}

__global__ __launch_bounds__(256) void fill_kernel(const int* __restrict__ dst,
                                                   int* ofs, int* elist)
{
    int e = blockIdx.x * 256 + threadIdx.x;
    if (e < EE) {
        int pos = atomicAdd(&ofs[dst[e]], 1);
        elist[pos] = e;
    }
}

// ======================= LayerNorm -> bf16 hi/lo =============================
__global__ __launch_bounds__(256) void ln_kernel(const float* __restrict__ x,
                                                 const float* __restrict__ w,
                                                 const float* __restrict__ b,
                                                 bf16* __restrict__ xh,
                                                 bf16* __restrict__ xl)
{
    int n = blockIdx.x, h = threadIdx.x;
    __shared__ float red[8];
    float v = x[n * HH + h];
    float s = v;
#pragma unroll
    for (int o = 16; o; o >>= 1) s += __shfl_xor_sync(0xffffffffu, s, o);
    if ((h & 31) == 0) red[h >> 5] = s;
    __syncthreads();
    float tot = 0.f;
#pragma unroll
    for (int i = 0; i < 8; i++) tot += red[i];
    float mu = tot * (1.f / HH);
    float dv = v - mu;
    float s2 = dv * dv;
#pragma unroll
    for (int o = 16; o; o >>= 1) s2 += __shfl_xor_sync(0xffffffffu, s2, o);
    __syncthreads();
    if ((h & 31) == 0) red[h >> 5] = s2;
    __syncthreads();
    float var = 0.f;
#pragma unroll
    for (int i = 0; i < 8; i++) var += red[i];
    var *= (1.f / HH);
    float xn = dv * rsqrtf(var + 1e-5f) * w[h] + b[h];
    bf16 hh2 = __float2bfloat16(xn);
    xh[n * HH + h] = hh2;
    xl[n * HH + h] = __float2bfloat16(xn - __bfloat162float(hh2));
}

// ======================= attention -> bf16 hi/lo =============================
__global__ __launch_bounds__(128) void attn_kernel(const float* __restrict__ q,
                                                   const float* __restrict__ k,
                                                   const float* __restrict__ vv,
                                                   bf16* __restrict__ oh,
                                                   bf16* __restrict__ ol)
{
    int blk = blockIdx.x;
    int b = blk >> 4;
    int hd = (blk >> 1) & 7;
    int i = (blk & 1) * 128 + threadIdx.x;
    __shared__ float ks[64][32];
    __shared__ float vs[64][32];
    float qr[32];
    const float* qrow = q + (size_t)(b * NN + i) * HH + hd * HD;
#pragma unroll
    for (int d = 0; d < 32; d++) qr[d] = qrow[d];
    float acc[32];
#pragma unroll
    for (int d = 0; d < 32; d++) acc[d] = 0.f;
    const float scale = rsqrtf((float)HD);

    for (int j0 = 0; j0 < NN; j0 += 64) {
        __syncthreads();
        for (int l = threadIdx.x; l < 512; l += 128) {
            int jr = l >> 3;
            int dc = (l & 7) * 4;
            size_t base = (size_t)(b * NN + j0 + jr) * HH + hd * HD + dc;
            *(float4*)&ks[jr][dc] = *(const float4*)&k[base];
            *(float4*)&vs[jr][dc] = *(const float4*)&vv[base];
        }
        __syncthreads();
        for (int j = 0; j < 64; j++) {
            float s = 0.f;
#pragma unroll
            for (int d = 0; d < 32; d++) s += qr[d] * ks[j][d];
            s = silu_f(s * scale);
#pragma unroll
            for (int d = 0; d < 32; d++) acc[d] += s * vs[j][d];
        }
    }
    size_t base = (size_t)(b * NN + i) * HH + hd * HD;
#pragma unroll
    for (int d = 0; d < 32; d++) {
        float val = acc[d] * (1.f / NN);
        bf16 h2 = __float2bfloat16(val);
        oh[base + d] = h2;
        ol[base + d] = __float2bfloat16(val - __bfloat162float(h2));
    }
}

// ======================= gather: x_agg + dvec (no atomics) ===================
__global__ __launch_bounds__(256) void gather_kernel(
    const bf16* __restrict__ vjh, const bf16* __restrict__ vjl,
    const float* __restrict__ s12, const float* __restrict__ vec,
    const float* __restrict__ dij, const int* __restrict__ src,
    const int* __restrict__ elist, const int* __restrict__ rowstart,
    bf16* __restrict__ xagh, bf16* __restrict__ xagl,
    float* __restrict__ dvec_out)
{
    int n = blockIdx.x, h = threadIdx.x;
    int beg = rowstart[n], end = rowstart[n + 1];
    float xa = 0.f;
    float dv[VD];
#pragma unroll
    for (int vd = 0; vd < VD; vd++) dv[vd] = 0.f;

    for (int i = beg; i < end; i++) {
        int e = elist[i];
        int s = src[e];
        float vje = __bfloat162float(vjh[(size_t)e * HH + h]) +
                    __bfloat162float(vjl[(size_t)e * HH + h]);
        xa += vje;
        float s1  = s12[(size_t)e * (2 * HH) + h];
        float s2v = s12[(size_t)e * (2 * HH) + HH + h];
#pragma unroll
        for (int vd = 0; vd < VD; vd++)
            dv[vd] += vec[(size_t)s * (VD * HH) + vd * HH + h] * s1
                    + s2v * dij[e * VD + vd];
    }
    bf16 hh = __float2bfloat16(xa);
    xagh[n * HH + h] = hh;
    xagl[n * HH + h] = __float2bfloat16(xa - __bfloat162float(hh));
#pragma unroll
    for (int vd = 0; vd < VD; vd++)
        dvec_out[(size_t)n * (VD * HH) + vd * HH + h] = dv[vd];
}

// ======================= finalize ============================================
__global__ __launch_bounds__(256) void finalize_kernel(const float* __restrict__ o,
                                                       const float* __restrict__ vp,
                                                       float* __restrict__ dx,
                                                       float* __restrict__ dvec)
{
    int n = blockIdx.x, h = threadIdx.x;
    float o1 = o[(size_t)n * (3 * HH) + h];
    float o2 = o[(size_t)n * (3 * HH) + HH + h];
    float o3 = o[(size_t)n * (3 * HH) + 2 * HH + h];
    float vsum = 0.f;
#pragma unroll
    for (int vd = 0; vd < VD; vd++)
        vsum += vp[(size_t)(n * VD + vd) * (2 * HH) + h];
    dx[n * HH + h] = vsum * o2 + o3;
#pragma unroll
    for (int vd = 0; vd < VD; vd++) {
        float vec3 = vp[(size_t)(n * VD + vd) * (2 * HH) + HH + h];
        dvec[(size_t)n * (VD * HH) + vd * HH + h] += vec3 * o1;
    }
}

// ======================= w_dot + df_ij =======================================
__global__ __launch_bounds__(256) void wdot_kernel(const float* __restrict__ T,
                                                   const float* __restrict__ S,
                                                   const float* __restrict__ ff,
                                                   const float* __restrict__ dij,
                                                   const int* __restrict__ src,
                                                   const int* __restrict__ dst,
                                                   float* __restrict__ df)
{
    int e = blockIdx.x, h = threadIdx.x;
    __shared__ float dsh[VD];
    if (h < VD) dsh[h] = dij[e * VD + h];
    __syncthreads();
    int s = src[e], t = dst[e];
    float tv[VD], sv[VD];
    float pT = 0.f, pS = 0.f;
#pragma unroll
    for (int vd = 0; vd < VD; vd++) {
        tv[vd] = T[(size_t)(t * VD + vd) * HH + h];
        sv[vd] = S[(size_t)(s * VD + vd) * HH + h];
        pT += tv[vd] * dsh[vd];
        pS += sv[vd] * dsh[vd];
    }
    float wd = 0.f;
#pragma unroll
    for (int vd = 0; vd < VD; vd++)
        wd += (tv[vd] - pT * dsh[vd]) * (sv[vd] - pS * dsh[vd]);
    df[(size_t)e * HH + h] = ff[(size_t)e * HH + h] * wd;
}

// ======================= launcher ============================================
extern "C" void kernel_launch(void* const* d_in, const int* in_sizes, int n_in,
                              void* d_out, int out_size)
{
    const float* x    = (const float*)d_in[0];
    const float* vec  = (const float*)d_in[1];
    const int*   ei   = (const int*)d_in[2];
    const float* r_ij = (const float*)d_in[3];
    const float* f_ij = (const float*)d_in[4];
    const float* d_ij = (const float*)d_in[5];
    const float* ln_w = (const float*)d_in[7];
    const float* ln_b = (const float*)d_in[8];
    const float* Wq   = (const float*)d_in[9];
    const float* Wk   = (const float*)d_in[10];
    const float* Wv   = (const float*)d_in[11];
    const float* Wao  = (const float*)d_in[12];
    const float* Wvec = (const float*)d_in[13];
    const float* Wdv  = (const float*)d_in[14];
    const float* bdv  = (const float*)d_in[15];
    const float* Ws   = (const float*)d_in[16];
    const float* bs   = (const float*)d_in[17];
    const float* Wo   = (const float*)d_in[18];
    const float* bo   = (const float*)d_in[19];
    const float* Wf   = (const float*)d_in[20];
    const float* bf   = (const float*)d_in[21];
    const float* Wsrc = (const float*)d_in[22];
    const float* Wtrg = (const float*)d_in[23];

    const int* src = ei;
    const int* dst = ei + EE;

    float* out      = (float*)d_out;
    float* out_dx   = out;
    float* out_dvec = out + (size_t)BN * HH;
    float* out_df   = out_dvec + (size_t)BN * VD * HH;

    float *p_q, *p_k, *p_vv, *p_v, *p_vp, *p_s12, *p_o, *p_T, *p_S, *p_ff;
    bf16 *p_xnh, *p_xnl, *p_vath, *p_vatl, *p_fijh, *p_fijl, *p_vjh, *p_vjl,
         *p_vech, *p_vecl, *p_xagh, *p_xagl, *p_wh, *p_wl;
    int *p_cnt, *p_ofs, *p_rowstart, *p_elist;
    cudaGetSymbolAddress((void**)&p_q,    g_q);
    cudaGetSymbolAddress((void**)&p_k,    g_k);
    cudaGetSymbolAddress((void**)&p_vv,   g_vv);
    cudaGetSymbolAddress((void**)&p_v,    g_v);
    cudaGetSymbolAddress((void**)&p_vp,   g_vp);
    cudaGetSymbolAddress((void**)&p_s12,  g_s12);
    cudaGetSymbolAddress((void**)&p_o,    g_o);
    cudaGetSymbolAddress((void**)&p_T,    g_T);
    cudaGetSymbolAddress((void**)&p_S,    g_S);
    cudaGetSymbolAddress((void**)&p_ff,   g_ff);
    cudaGetSymbolAddress((void**)&p_xnh,  g_xnh);
    cudaGetSymbolAddress((void**)&p_xnl,  g_xnl);
    cudaGetSymbolAddress((void**)&p_vath, g_vath);
    cudaGetSymbolAddress((void**)&p_vatl, g_vatl);
    cudaGetSymbolAddress((void**)&p_fijh, g_fijh);
    cudaGetSymbolAddress((void**)&p_fijl, g_fijl);
    cudaGetSymbolAddress((void**)&p_vjh,  g_vjh);
    cudaGetSymbolAddress((void**)&p_vjl,  g_vjl);
    cudaGetSymbolAddress((void**)&p_vech, g_vech);
    cudaGetSymbolAddress((void**)&p_vecl, g_vecl);
    cudaGetSymbolAddress((void**)&p_xagh, g_xagh);
    cudaGetSymbolAddress((void**)&p_xagl, g_xagl);
    cudaGetSymbolAddress((void**)&p_wh,   g_wh);
    cudaGetSymbolAddress((void**)&p_wl,   g_wl);
    cudaGetSymbolAddress((void**)&p_cnt,      g_cnt);
    cudaGetSymbolAddress((void**)&p_ofs,      g_ofs);
    cudaGetSymbolAddress((void**)&p_rowstart, g_rowstart);
    cudaGetSymbolAddress((void**)&p_elist,    g_elist);

    cudaFuncSetAttribute(mma_gemm<0>, cudaFuncAttributeMaxDynamicSharedMemorySize, MG_SMEM);
    cudaFuncSetAttribute(mma_gemm<1>, cudaFuncAttributeMaxDynamicSharedMemorySize, MG_SMEM);
    cudaFuncSetAttribute(mma_gemm<2>, cudaFuncAttributeMaxDynamicSharedMemorySize, MG_SMEM);
    cudaFuncSetAttribute(mma_gemm<3>, cudaFuncAttributeMaxDynamicSharedMemorySize, MG_SMEM);

    // CSR build
    cudaMemsetAsync(p_cnt, 0, BN * sizeof(int), 0);
    hist_kernel<<<EE / 256, 256>>>(dst, p_cnt);
    scan_kernel<<<1, 1024>>>(p_cnt, p_rowstart, p_ofs);
    fill_kernel<<<EE / 256, 256>>>(dst, p_ofs, p_elist);

    // weight prep
    {
        WPrep wp{};
        const float* srcs[11] = {Wq, Wk, Wv, Wao, Wdv, Wf, Ws, Wvec, Wo, Wtrg, Wsrc};
        int ns[11]   = {256, 256, 256, 256, 256, 256, 512, 512, 768, 256, 256};
        int offs[11] = {OFF_WQ, OFF_WK, OFF_WV, OFF_WAO, OFF_WDV, OFF_WF,
                        OFF_WS, OFF_WVEC, OFF_WO, OFF_WTRG, OFF_WSRC};
        for (int i = 0; i < 11; i++) { wp.src[i] = srcs[i]; wp.N[i] = ns[i]; wp.off[i] = offs[i]; }
        wprep_kernel<<<dim3(768, 11), 256>>>(wp, p_wh, p_wl);
    }

    // input converts
    conv_kernel<<<(EE * HH / 4 + 255) / 256, 256>>>(f_ij, p_fijh, p_fijl, EE * HH / 4);
    conv_kernel<<<(BN * VD * HH / 4 + 255) / 256, 256>>>(vec, p_vech, p_vecl, BN * VD * HH / 4);

    // 1. LayerNorm -> bf16 hi/lo
    ln_kernel<<<BN, 256>>>(x, ln_w, ln_b, p_xnh, p_xnl);

    // 2. q/k/v (z=3)
    {
        TcB g{};
        g.Bh[0] = p_wh + (size_t)OFF_WQ * HH; g.Bl[0] = p_wl + (size_t)OFF_WQ * HH; g.C[0] = p_q;
        g.Bh[1] = p_wh + (size_t)OFF_WK * HH; g.Bl[1] = p_wl + (size_t)OFF_WK * HH; g.C[1] = p_k;
        g.Bh[2] = p_wh + (size_t)OFF_WV * HH; g.Bl[2] = p_wl + (size_t)OFF_WV * HH; g.C[2] = p_vv;
        mma_gemm<0><<<dim3(2, 16, 3), 256, MG_SMEM>>>(p_xnh, p_xnl, g, HH,
                                                      nullptr, nullptr, nullptr, nullptr, nullptr);
    }

    // 3. attention
    attn_kernel<<<BB * NHD * 2, 128>>>(p_q, p_k, p_vv, p_vath, p_vatl);

    // 4. v = vatt @ Wao
    {
        TcB g{};
        g.Bh[0] = p_wh + (size_t)OFF_WAO * HH; g.Bl[0] = p_wl + (size_t)OFF_WAO * HH; g.C[0] = p_v;
        mma_gemm<0><<<dim3(2, 16, 1), 256, MG_SMEM>>>(p_vath, p_vatl, g, HH,
                                                      nullptr, nullptr, nullptr, nullptr, nullptr);
    }

    // 5a. ff = silu(f_ij @ Wf + bf)
    {
        TcB g{};
        g.Bh[0] = p_wh + (size_t)OFF_WF * HH; g.Bl[0] = p_wl + (size_t)OFF_WF * HH;
        g.bias[0] = bf; g.C[0] = p_ff;
        mma_gemm<2><<<dim3(2, 128, 1), 256, MG_SMEM>>>(p_fijh, p_fijl, g, HH,
                                                       nullptr, nullptr, nullptr, nullptr, nullptr);
    }

    // 5b. vj = silu(f_ij @ Wdv + bdv) * cut * v[src]  -> bf16 hi/lo (MODE 3)
    {
        TcB g{};
        g.Bh[0] = p_wh + (size_t)OFF_WDV * HH; g.Bl[0] = p_wl + (size_t)OFF_WDV * HH;
        g.bias[0] = bdv;
        mma_gemm<3><<<dim3(2, 128, 1), 256, MG_SMEM>>>(p_fijh, p_fijl, g, HH,
                                                       p_v, src, r_ij, p_vjh, p_vjl);
    }

    // 6. s12 = silu(v_j @ Ws + bs)   N=512
    {
        TcB g{};
        g.Bh[0] = p_wh + (size_t)OFF_WS * HH; g.Bl[0] = p_wl + (size_t)OFF_WS * HH;
        g.bias[0] = bs; g.C[0] = p_s12;
        mma_gemm<2><<<dim3(4, 128, 1), 256, MG_SMEM>>>(p_vjh, p_vjl, g, 2 * HH,
                                                       nullptr, nullptr, nullptr, nullptr, nullptr);
    }

    // 7. vp = vec @ Wvec   N=512
    {
        TcB g{};
        g.Bh[0] = p_wh + (size_t)OFF_WVEC * HH; g.Bl[0] = p_wl + (size_t)OFF_WVEC * HH;
        g.C[0] = p_vp;
        mma_gemm<0><<<dim3(4, 128, 1), 256, MG_SMEM>>>(p_vech, p_vecl, g, 2 * HH,
                                                       nullptr, nullptr, nullptr, nullptr, nullptr);
    }

    // 8. gather: x_agg (bf16 hi/lo) + dvec
    gather_kernel<<<BN, 256>>>(p_vjh, p_vjl, p_s12, vec, d_ij, src,
                               p_elist, p_rowstart, p_xagh, p_xagl, out_dvec);

    // 9. o = x_agg @ Wo + bo  (N=768)
    {
        TcB g{};
        g.Bh[0] = p_wh + (size_t)OFF_WO * HH; g.Bl[0] = p_wl + (size_t)OFF_WO * HH;
        g.bias[0] = bo; g.C[0] = p_o;
        mma_gemm<1><<<dim3(6, 16, 1), 256, MG_SMEM>>>(p_xagh, p_xagl, g, 3 * HH,
                                                      nullptr, nullptr, nullptr, nullptr, nullptr);
    }

    // 10. finalize
    finalize_kernel<<<BN, 256>>>(p_o, p_vp, out_dx, out_dvec);

    // 11. T/S fused (z=2)
    {
        TcB g{};
        g.Bh[0] = p_wh + (size_t)OFF_WTRG * HH; g.Bl[0] = p_wl + (size_t)OFF_WTRG * HH; g.C[0] = p_T;
        g.Bh[1] = p_wh + (size_t)OFF_WSRC * HH; g.Bl[1] = p_wl + (size_t)OFF_WSRC * HH; g.C[1] = p_S;
        mma_gemm<0><<<dim3(2, 128, 2), 256, MG_SMEM>>>(p_vech, p_vecl, g, HH,
                                                       nullptr, nullptr, nullptr, nullptr, nullptr);
    }

    // 12. w_dot + df_ij
    wdot_kernel<<<EE, 256>>>(p_T, p_S, p_ff, d_ij, src, dst, out_df);
}

// round 6
// speedup vs baseline: 2.1659x; 1.0507x over previous
#include <cuda_runtime.h>
#include <cuda_bf16.h>
#include <cstdint>

// Problem constants
#define BB 8
#define NN 256
#define BN 2048          // BB*NN
#define EE 16384
#define HH 256
#define NHD 8
#define HD 32
#define VD 8

typedef __nv_bfloat16 bf16;

// ---------------- fp32 scratch ------------------------------------------------
__device__ float g_q   [BN*HH];
__device__ float g_k   [BN*HH];
__device__ float g_vv  [BN*HH];
__device__ float g_v   [BN*HH];
__device__ float g_vp  [BN*VD*2*HH];
__device__ float g_s12 [EE*2*HH];
__device__ float g_o   [BN*3*HH];
__device__ float g_T   [BN*VD*HH];
__device__ float g_S   [BN*VD*HH];
__device__ float g_ff  [EE*HH];
__device__ float g_zb  [3*HH];          // zero bias (static zero-init)

// ---------------- bf16 hi/lo scratch -----------------------------------------
__device__ bf16 g_xnh [BN*HH],    g_xnl [BN*HH];
__device__ bf16 g_vath[BN*HH],    g_vatl[BN*HH];
__device__ bf16 g_fijh[EE*HH],    g_fijl[EE*HH];
__device__ bf16 g_vjh [EE*HH],    g_vjl [EE*HH];
__device__ bf16 g_vech[BN*VD*HH], g_vecl[BN*VD*HH];
__device__ bf16 g_xagh[BN*HH],    g_xagl[BN*HH];
#define WROWS 3840
__device__ bf16 g_wh[WROWS*HH], g_wl[WROWS*HH];

// ---------------- CSR scratch -------------------------------------------------
__device__ int g_rowstart[BN + 1];
__device__ int g_elist[EE];

// weight row offsets within g_wh/g_wl
#define OFF_WQ   0
#define OFF_WK   256
#define OFF_WV   512
#define OFF_WAO  768
#define OFF_WDV  1024
#define OFF_WF   1280
#define OFF_WS   1536
#define OFF_WVEC 2048
#define OFF_WO   2560
#define OFF_WTRG 3328
#define OFF_WSRC 3584

__device__ __forceinline__ float silu_f(float x) { return x / (1.f + __expf(-x)); }
__device__ __forceinline__ float cut_f(float rr) {
    return (rr < 5.f) ? 0.5f * (cosf(rr * 0.6283185307179586f) + 1.f) : 0.f;
}

__device__ __forceinline__ uint32_t smem_u32(const void* p) {
    uint32_t a;
    asm("{ .reg .u64 t; cvta.to.shared.u64 t, %1; cvt.u32.u64 %0, t; }" : "=r"(a) : "l"(p));
    return a;
}

// ---------------- mma.sync / ldmatrix / cp.async wrappers --------------------
__device__ __forceinline__ void ldsm4(uint32_t* r, uint32_t addr) {
    asm volatile("ldmatrix.sync.aligned.m8n8.x4.shared.b16 {%0,%1,%2,%3}, [%4];"
                 : "=r"(r[0]), "=r"(r[1]), "=r"(r[2]), "=r"(r[3]) : "r"(addr));
}
__device__ __forceinline__ void mma_bf16(float* d, const uint32_t* a, const uint32_t* b) {
    asm volatile("mma.sync.aligned.m16n8k16.row.col.f32.bf16.bf16.f32 "
                 "{%0,%1,%2,%3}, {%4,%5,%6,%7}, {%8,%9}, {%0,%1,%2,%3};"
                 : "+f"(d[0]), "+f"(d[1]), "+f"(d[2]), "+f"(d[3])
                 : "r"(a[0]), "r"(a[1]), "r"(a[2]), "r"(a[3]), "r"(b[0]), "r"(b[1]));
}
#define CP_COMMIT() asm volatile("cp.async.commit_group;" ::: "memory")

// =============================================================================
// Unified job-table GEMM: each launch carries up to 7 jobs. Block -> job via
// tileOfs prefix. Mode 0: C = [silu](A@W^T + bias) fp32. Mode 1 (whole launch):
// vj epilogue silu(acc+bias)*cut(r[row])*v[src[row]][col] -> bf16 hi/lo.
// =============================================================================
struct GJob {
    const bf16 *Ah, *Al, *Bh, *Bl;
    const float* bias;
    float* C;
    int Nfull, colTiles, silu, tileOfs;
};
struct GArgs {
    GJob jobs[7];
    int njobs;
    int mode;
    const float* vsrc; const int* srcidx; const float* rij;
    bf16 *Oh, *Ol;
};

#define MG_SMEM 131072

__device__ __forceinline__ void cp_tile(uint32_t dst_s, const bf16* __restrict__ src,
                                        int rowbase, int kc, int tid)
{
    const char* g = (const char*)(src + (size_t)rowbase * HH + kc * 64);
#pragma unroll
    for (int it = 0; it < 4; it++) {
        int u   = tid + it * 256;
        int row = u >> 3;
        int ui  = u & 7;
        uint32_t off = row * 128 + ui * 16;
        off ^= (off >> 3) & 0x70;
        asm volatile("cp.async.cg.shared.global [%0], [%1], 16;"
                     :: "r"(dst_s + off), "l"(g + (size_t)row * 512 + ui * 16));
    }
}

__device__ __forceinline__ void cp_chunk(uint32_t sbase,
    const bf16* Ah, const bf16* Al, const bf16* Bh, const bf16* Bl,
    int rowA, int rowB, int kc, int tid)
{
    cp_tile(sbase,         Ah, rowA, kc, tid);
    cp_tile(sbase + 16384, Al, rowA, kc, tid);
    cp_tile(sbase + 32768, Bh, rowB, kc, tid);
    cp_tile(sbase + 49152, Bl, rowB, kc, tid);
}

__global__ __launch_bounds__(256) void gemm_kernel(GArgs P)
{
    extern __shared__ uint8_t smem[];
    const int tid = threadIdx.x, wid = tid >> 5, lane = tid & 31;

    int j = 0;
#pragma unroll
    for (int jj = 1; jj < 7; jj++)
        if (jj < P.njobs && (int)blockIdx.x >= P.jobs[jj].tileOfs) j = jj;
    const GJob job = P.jobs[j];
    const int local = blockIdx.x - job.tileOfs;
    const int rowA = (local / job.colTiles) * 128;
    const int rowB = (local % job.colTiles) * 128;

    const bf16* __restrict__ Ah = job.Ah;
    const bf16* __restrict__ Al = job.Al;
    const bf16* __restrict__ Bh = job.Bh;
    const bf16* __restrict__ Bl = job.Bl;

    const int wr = wid >> 2, wc = wid & 3;

    uint32_t aoff[4], boff[2];
#pragma unroll
    for (int i = 0; i < 4; i++)
        aoff[i] = (uint32_t)((wr * 64 + i * 16 + (lane & 15)) * 128 + (lane >> 4) * 16);
    {
        int grp = lane >> 3, lr = lane & 7;
#pragma unroll
        for (int j2 = 0; j2 < 2; j2++)
            boff[j2] = (uint32_t)((wc * 32 + j2 * 16 + (grp >> 1) * 8 + lr) * 128
                                  + (grp & 1) * 16);
    }

    const uint32_t sb = smem_u32(smem);

    float acc[4][4][4];
#pragma unroll
    for (int i = 0; i < 4; i++)
#pragma unroll
        for (int jj = 0; jj < 4; jj++)
#pragma unroll
            for (int r = 0; r < 4; r++) acc[i][jj][r] = 0.f;

    cp_chunk(sb,         Ah, Al, Bh, Bl, rowA, rowB, 0, tid); CP_COMMIT();
    cp_chunk(sb + 65536, Ah, Al, Bh, Bl, rowA, rowB, 1, tid); CP_COMMIT();

    int buf = 0;
    for (int kc = 0; kc < 4; kc++) {
        if (kc < 3) asm volatile("cp.async.wait_group 1;" ::: "memory");
        else        asm volatile("cp.async.wait_group 0;" ::: "memory");
        __syncthreads();
        const uint32_t base = sb + buf * 65536;
#pragma unroll
        for (int ks = 0; ks < 4; ks++) {
            const uint32_t kb = ks * 32;
            uint32_t ahf[4][4], alf[4][4], bhf[2][4], blf[2][4];
#pragma unroll
            for (int i = 0; i < 4; i++) {
                uint32_t o = aoff[i] + kb; o ^= (o >> 3) & 0x70;
                ldsm4(ahf[i], base + o);
                ldsm4(alf[i], base + 16384 + o);
            }
#pragma unroll
            for (int j2 = 0; j2 < 2; j2++) {
                uint32_t o = boff[j2] + kb; o ^= (o >> 3) & 0x70;
                ldsm4(bhf[j2], base + 32768 + o);
                ldsm4(blf[j2], base + 49152 + o);
            }
#pragma unroll
            for (int i = 0; i < 4; i++)
#pragma unroll
                for (int jj = 0; jj < 4; jj++) {
                    const uint32_t* b_hi = &bhf[jj >> 1][(jj & 1) * 2];
                    const uint32_t* b_lo = &blf[jj >> 1][(jj & 1) * 2];
                    mma_bf16(acc[i][jj], ahf[i], b_hi);
                    mma_bf16(acc[i][jj], ahf[i], b_lo);
                    mma_bf16(acc[i][jj], alf[i], b_hi);
                }
        }
        __syncthreads();
        if (kc + 2 <= 3) {
            cp_chunk(sb + buf * 65536, Ah, Al, Bh, Bl, rowA, rowB, kc + 2, tid);
            CP_COMMIT();
        }
        buf ^= 1;
    }

    const float* bias = job.bias;
    const int r0 = lane >> 2, c0 = (lane & 3) * 2;

    if (P.mode == 1) {
        __nv_bfloat162* OH = (__nv_bfloat162*)P.Oh;
        __nv_bfloat162* OL = (__nv_bfloat162*)P.Ol;
#pragma unroll
        for (int i = 0; i < 4; i++) {
            const int row0 = rowA + wr * 64 + i * 16 + r0;
            const int row1 = row0 + 8;
            const int s0 = P.srcidx[row0], s1i = P.srcidx[row1];
            const float cut0 = cut_f(P.rij[row0]);
            const float cut1 = cut_f(P.rij[row1]);
#pragma unroll
            for (int jj = 0; jj < 4; jj++) {
                const int gcol = rowB + wc * 32 + jj * 8 + c0;
                const float b0 = bias[gcol], b1 = bias[gcol + 1];
                float v0 = silu_f(acc[i][jj][0] + b0) * cut0 * P.vsrc[(size_t)s0 * HH + gcol];
                float v1 = silu_f(acc[i][jj][1] + b1) * cut0 * P.vsrc[(size_t)s0 * HH + gcol + 1];
                float v2 = silu_f(acc[i][jj][2] + b0) * cut1 * P.vsrc[(size_t)s1i * HH + gcol];
                float v3 = silu_f(acc[i][jj][3] + b1) * cut1 * P.vsrc[(size_t)s1i * HH + gcol + 1];
                bf16 h0 = __float2bfloat16(v0), h1 = __float2bfloat16(v1);
                bf16 h2 = __float2bfloat16(v2), h3 = __float2bfloat16(v3);
                bf16 l0 = __float2bfloat16(v0 - __bfloat162float(h0));
                bf16 l1 = __float2bfloat16(v1 - __bfloat162float(h1));
                bf16 l2 = __float2bfloat16(v2 - __bfloat162float(h2));
                bf16 l3 = __float2bfloat16(v3 - __bfloat162float(h3));
                OH[(size_t)row0 * 128 + (gcol >> 1)] = __nv_bfloat162(h0, h1);
                OL[(size_t)row0 * 128 + (gcol >> 1)] = __nv_bfloat162(l0, l1);
                OH[(size_t)row1 * 128 + (gcol >> 1)] = __nv_bfloat162(h2, h3);
                OL[(size_t)row1 * 128 + (gcol >> 1)] = __nv_bfloat162(l2, l3);
            }
        }
    } else {
        float* __restrict__ C = job.C;
        const int Nfull = job.Nfull;
        const int do_silu = job.silu;
#pragma unroll
        for (int i = 0; i < 4; i++) {
            const int grow = rowA + wr * 64 + i * 16 + r0;
#pragma unroll
            for (int jj = 0; jj < 4; jj++) {
                const int gcol = rowB + wc * 32 + jj * 8 + c0;
                float b0 = bias[gcol], b1 = bias[gcol + 1];
                float v0 = acc[i][jj][0] + b0, v1 = acc[i][jj][1] + b1;
                float v2 = acc[i][jj][2] + b0, v3 = acc[i][jj][3] + b1;
                if (do_silu) {
                    v0 = silu_f(v0); v1 = silu_f(v1); v2 = silu_f(v2); v3 = silu_f(v3);
                }
                *(float2*)(C + (size_t)grow * Nfull + gcol)       = make_float2(v0, v1);
                *(float2*)(C + (size_t)(grow + 8) * Nfull + gcol) = make_float2(v2, v3);
            }
        }
    }
}

// =============================================================================
// prep_kernel: wprep (8448) | conv fij (4096) | conv vec (4096) | ln (2048) | CSR (1)
// =============================================================================
struct PrepArgs {
    const float* wsrc[11]; int wN[11]; int woff[11];
    const float* f_ij; const float* vec; const float* x;
    const float* ln_w; const float* ln_b; const int* dst;
};

__device__ __forceinline__ void conv_body(int i, const float* __restrict__ in,
                                          bf16* hi, bf16* lo)
{
    float4 v = ((const float4*)in)[i];
    bf16 h0 = __float2bfloat16(v.x), h1 = __float2bfloat16(v.y);
    bf16 h2 = __float2bfloat16(v.z), h3 = __float2bfloat16(v.w);
    bf16 l0 = __float2bfloat16(v.x - __bfloat162float(h0));
    bf16 l1 = __float2bfloat16(v.y - __bfloat162float(h1));
    bf16 l2 = __float2bfloat16(v.z - __bfloat162float(h2));
    bf16 l3 = __float2bfloat16(v.w - __bfloat162float(h3));
    __nv_bfloat162* hp = (__nv_bfloat162*)hi;
    __nv_bfloat162* lp = (__nv_bfloat162*)lo;
    hp[2 * i]     = __nv_bfloat162(h0, h1);
    hp[2 * i + 1] = __nv_bfloat162(h2, h3);
    lp[2 * i]     = __nv_bfloat162(l0, l1);
    lp[2 * i + 1] = __nv_bfloat162(l2, l3);
}

#define PREP_WP   8448
#define PREP_CF   4096
#define PREP_CV   4096
#define PREP_LN   2048
#define PREP_TOT  (PREP_WP + PREP_CF + PREP_CV + PREP_LN + 1)

__global__ __launch_bounds__(256) void prep_kernel(PrepArgs P)
{
    __shared__ int csr_s[BN];
    __shared__ float red[8];
    int bx = blockIdx.x;
    const int t = threadIdx.x;

    if (bx < PREP_WP) {               // weight prep
        int w = bx / 768, n = bx % 768;
        if (n < P.wN[w]) {
            float v = P.wsrc[w][(size_t)t * P.wN[w] + n];
            bf16 h = __float2bfloat16(v);
            bf16 l = __float2bfloat16(v - __bfloat162float(h));
            size_t o = (size_t)(P.woff[w] + n) * HH + t;
            g_wh[o] = h; g_wl[o] = l;
        }
        return;
    }
    bx -= PREP_WP;
    if (bx < PREP_CF) { conv_body(bx * 256 + t, P.f_ij, g_fijh, g_fijl); return; }
    bx -= PREP_CF;
    if (bx < PREP_CV) { conv_body(bx * 256 + t, P.vec, g_vech, g_vecl); return; }
    bx -= PREP_CV;
    if (bx < PREP_LN) {               // LayerNorm
        int n = bx;
        float v = P.x[n * HH + t];
        float s = v;
#pragma unroll
        for (int o = 16; o; o >>= 1) s += __shfl_xor_sync(0xffffffffu, s, o);
        if ((t & 31) == 0) red[t >> 5] = s;
        __syncthreads();
        float tot = 0.f;
#pragma unroll
        for (int i = 0; i < 8; i++) tot += red[i];
        float mu = tot * (1.f / HH);
        float dv = v - mu;
        float s2 = dv * dv;
#pragma unroll
        for (int o = 16; o; o >>= 1) s2 += __shfl_xor_sync(0xffffffffu, s2, o);
        __syncthreads();
        if ((t & 31) == 0) red[t >> 5] = s2;
        __syncthreads();
        float var = 0.f;
#pragma unroll
        for (int i = 0; i < 8; i++) var += red[i];
        var *= (1.f / HH);
        float xn = dv * rsqrtf(var + 1e-5f) * P.ln_w[t] + P.ln_b[t];
        bf16 hh2 = __float2bfloat16(xn);
        g_xnh[n * HH + t] = hh2;
        g_xnl[n * HH + t] = __float2bfloat16(xn - __bfloat162float(hh2));
        return;
    }

    // ---- CSR build (single block) ----
    for (int i = t; i < BN; i += 256) csr_s[i] = 0;
    __syncthreads();
    const int4* d4 = (const int4*)P.dst;
#pragma unroll
    for (int i = 0; i < 16; i++) {
        int4 v = d4[t * 16 + i];
        atomicAdd(&csr_s[v.x], 1); atomicAdd(&csr_s[v.y], 1);
        atomicAdd(&csr_s[v.z], 1); atomicAdd(&csr_s[v.w], 1);
    }
    __syncthreads();
    for (int d = 1; d < BN; d <<= 1) {
        for (int i = t; i < BN / (2 * d); i += 256) {
            int idx = (i + 1) * 2 * d - 1;
            csr_s[idx] += csr_s[idx - d];
        }
        __syncthreads();
    }
    if (t == 0) { g_rowstart[BN] = csr_s[BN - 1]; csr_s[BN - 1] = 0; }
    __syncthreads();
    for (int d = BN / 2; d >= 1; d >>= 1) {
        for (int i = t; i < BN / (2 * d); i += 256) {
            int idx = (i + 1) * 2 * d - 1;
            int a = csr_s[idx - d];
            csr_s[idx - d] = csr_s[idx];
            csr_s[idx] += a;
        }
        __syncthreads();
    }
    for (int i = t; i < BN; i += 256) g_rowstart[i] = csr_s[i];
    __syncthreads();
#pragma unroll
    for (int i = 0; i < 16; i++) {
        int4 v = d4[t * 16 + i];
        int e = t * 64 + i * 4;
        int p0 = atomicAdd(&csr_s[v.x], 1); g_elist[p0] = e;
        int p1 = atomicAdd(&csr_s[v.y], 1); g_elist[p1] = e + 1;
        int p2 = atomicAdd(&csr_s[v.z], 1); g_elist[p2] = e + 2;
        int p3 = atomicAdd(&csr_s[v.w], 1); g_elist[p3] = e + 3;
    }
}

// =============================================================================
// attn (blocks 0..63) + wdot (blocks 64..64+EE)
// =============================================================================
__global__ __launch_bounds__(256) void attn_wdot_kernel(
    const int* __restrict__ src, const int* __restrict__ dst,
    const float* __restrict__ dij, const float* __restrict__ rij_unused,
    float* __restrict__ df)
{
    __shared__ float ks[64][32];
    __shared__ float vs[64][32];
    __shared__ float dsh[VD];

    if (blockIdx.x < 64) {
        int b = blockIdx.x >> 3;
        int hd = blockIdx.x & 7;
        int i = threadIdx.x;
        float qr[32];
        const float* qrow = g_q + (size_t)(b * NN + i) * HH + hd * HD;
#pragma unroll
        for (int d = 0; d < 32; d++) qr[d] = qrow[d];
        float acc[32];
#pragma unroll
        for (int d = 0; d < 32; d++) acc[d] = 0.f;
        const float scale = rsqrtf((float)HD);

        for (int j0 = 0; j0 < NN; j0 += 64) {
            __syncthreads();
            for (int l = threadIdx.x; l < 512; l += 256) {
                int jr = l >> 3;
                int dc = (l & 7) * 4;
                size_t base = (size_t)(b * NN + j0 + jr) * HH + hd * HD + dc;
                *(float4*)&ks[jr][dc] = *(const float4*)&g_k[base];
                *(float4*)&vs[jr][dc] = *(const float4*)&g_vv[base];
            }
            __syncthreads();
            for (int j = 0; j < 64; j++) {
                float s = 0.f;
#pragma unroll
                for (int d = 0; d < 32; d++) s += qr[d] * ks[j][d];
                s = silu_f(s * scale);
#pragma unroll
                for (int d = 0; d < 32; d++) acc[d] += s * vs[j][d];
            }
        }
        size_t base = (size_t)(b * NN + i) * HH + hd * HD;
#pragma unroll
        for (int d = 0; d < 32; d++) {
            float val = acc[d] * (1.f / NN);
            bf16 h2 = __float2bfloat16(val);
            g_vath[base + d] = h2;
            g_vatl[base + d] = __float2bfloat16(val - __bfloat162float(h2));
        }
        return;
    }

    int e = blockIdx.x - 64;
    int h = threadIdx.x;
    if (h < VD) dsh[h] = dij[e * VD + h];
    __syncthreads();
    int s = src[e], tt = dst[e];
    float tv[VD], sv[VD];
    float pT = 0.f, pS = 0.f;
#pragma unroll
    for (int vd = 0; vd < VD; vd++) {
        tv[vd] = g_T[(size_t)(tt * VD + vd) * HH + h];
        sv[vd] = g_S[(size_t)(s * VD + vd) * HH + h];
        pT += tv[vd] * dsh[vd];
        pS += sv[vd] * dsh[vd];
    }
    float wd = 0.f;
#pragma unroll
    for (int vd = 0; vd < VD; vd++)
        wd += (tv[vd] - pT * dsh[vd]) * (sv[vd] - pS * dsh[vd]);
    df[(size_t)e * HH + h] = g_ff[(size_t)e * HH + h] * wd;
}

// ======================= gather: x_agg + dvec (no atomics) ===================
__global__ __launch_bounds__(256) void gather_kernel(
    const float* __restrict__ s12, const float* __restrict__ vec,
    const float* __restrict__ dij, const int* __restrict__ src,
    float* __restrict__ dvec_out)
{
    int n = blockIdx.x, h = threadIdx.x;
    int beg = g_rowstart[n], end = g_rowstart[n + 1];
    float xa = 0.f;
    float dv[VD];
#pragma unroll
    for (int vd = 0; vd < VD; vd++) dv[vd] = 0.f;

    for (int i = beg; i < end; i++) {
        int e = g_elist[i];
        int s = src[e];
        float vje = __bfloat162float(g_vjh[(size_t)e * HH + h]) +
                    __bfloat162float(g_vjl[(size_t)e * HH + h]);
        xa += vje;
        float s1  = s12[(size_t)e * (2 * HH) + h];
        float s2v = s12[(size_t)e * (2 * HH) + HH + h];
#pragma unroll
        for (int vd = 0; vd < VD; vd++)
            dv[vd] += vec[(size_t)s * (VD * HH) + vd * HH + h] * s1
                    + s2v * dij[e * VD + vd];
    }
    bf16 hh = __float2bfloat16(xa);
    g_xagh[n * HH + h] = hh;
    g_xagl[n * HH + h] = __float2bfloat16(xa - __bfloat162float(hh));
#pragma unroll
    for (int vd = 0; vd < VD; vd++)
        dvec_out[(size_t)n * (VD * HH) + vd * HH + h] = dv[vd];
}

// ======================= finalize ============================================
__global__ __launch_bounds__(256) void finalize_kernel(float* __restrict__ dx,
                                                       float* __restrict__ dvec)
{
    int n = blockIdx.x, h = threadIdx.x;
    float o1 = g_o[(size_t)n * (3 * HH) + h];
    float o2 = g_o[(size_t)n * (3 * HH) + HH + h];
    float o3 = g_o[(size_t)n * (3 * HH) + 2 * HH + h];
    float vsum = 0.f;
#pragma unroll
    for (int vd = 0; vd < VD; vd++)
        vsum += g_vp[(size_t)(n * VD + vd) * (2 * HH) + h];
    dx[n * HH + h] = vsum * o2 + o3;
#pragma unroll
    for (int vd = 0; vd < VD; vd++) {
        float vec3 = g_vp[(size_t)(n * VD + vd) * (2 * HH) + HH + h];
        dvec[(size_t)n * (VD * HH) + vd * HH + h] += vec3 * o1;
    }
}

// ======================= launcher ============================================
extern "C" void kernel_launch(void* const* d_in, const int* in_sizes, int n_in,
                              void* d_out, int out_size)
{
    const float* x    = (const float*)d_in[0];
    const float* vec  = (const float*)d_in[1];
    const int*   ei   = (const int*)d_in[2];
    const float* r_ij = (const float*)d_in[3];
    const float* f_ij = (const float*)d_in[4];
    const float* d_ij = (const float*)d_in[5];
    const float* ln_w = (const float*)d_in[7];
    const float* ln_b = (const float*)d_in[8];
    const float* Wq   = (const float*)d_in[9];
    const float* Wk   = (const float*)d_in[10];
    const float* Wv   = (const float*)d_in[11];
    const float* Wao  = (const float*)d_in[12];
    const float* Wvec = (const float*)d_in[13];
    const float* Wdv  = (const float*)d_in[14];
    const float* bdv  = (const float*)d_in[15];
    const float* Ws   = (const float*)d_in[16];
    const float* bs   = (const float*)d_in[17];
    const float* Wo   = (const float*)d_in[18];
    const float* bo   = (const float*)d_in[19];
    const float* Wf   = (const float*)d_in[20];
    const float* bf   = (const float*)d_in[21];
    const float* Wsrc = (const float*)d_in[22];
    const float* Wtrg = (const float*)d_in[23];

    const int* src = ei;
    const int* dst = ei + EE;

    float* out      = (float*)d_out;
    float* out_dx   = out;
    float* out_dvec = out + (size_t)BN * HH;
    float* out_df   = out_dvec + (size_t)BN * VD * HH;

    float *p_q, *p_k, *p_vv, *p_v, *p_vp, *p_s12, *p_o, *p_T, *p_S, *p_ff, *p_zb;
    bf16 *p_xnh, *p_xnl, *p_vath, *p_vatl, *p_fijh, *p_fijl, *p_vjh, *p_vjl,
         *p_vech, *p_vecl, *p_xagh, *p_xagl, *p_wh, *p_wl;
    cudaGetSymbolAddress((void**)&p_q,    g_q);
    cudaGetSymbolAddress((void**)&p_k,    g_k);
    cudaGetSymbolAddress((void**)&p_vv,   g_vv);
    cudaGetSymbolAddress((void**)&p_v,    g_v);
    cudaGetSymbolAddress((void**)&p_vp,   g_vp);
    cudaGetSymbolAddress((void**)&p_s12,  g_s12);
    cudaGetSymbolAddress((void**)&p_o,    g_o);
    cudaGetSymbolAddress((void**)&p_T,    g_T);
    cudaGetSymbolAddress((void**)&p_S,    g_S);
    cudaGetSymbolAddress((void**)&p_ff,   g_ff);
    cudaGetSymbolAddress((void**)&p_zb,   g_zb);
    cudaGetSymbolAddress((void**)&p_xnh,  g_xnh);
    cudaGetSymbolAddress((void**)&p_xnl,  g_xnl);
    cudaGetSymbolAddress((void**)&p_vath, g_vath);
    cudaGetSymbolAddress((void**)&p_vatl, g_vatl);
    cudaGetSymbolAddress((void**)&p_fijh, g_fijh);
    cudaGetSymbolAddress((void**)&p_fijl, g_fijl);
    cudaGetSymbolAddress((void**)&p_vjh,  g_vjh);
    cudaGetSymbolAddress((void**)&p_vjl,  g_vjl);
    cudaGetSymbolAddress((void**)&p_vech, g_vech);
    cudaGetSymbolAddress((void**)&p_vecl, g_vecl);
    cudaGetSymbolAddress((void**)&p_xagh, g_xagh);
    cudaGetSymbolAddress((void**)&p_xagl, g_xagl);
    cudaGetSymbolAddress((void**)&p_wh,   g_wh);
    cudaGetSymbolAddress((void**)&p_wl,   g_wl);

    cudaFuncSetAttribute(gemm_kernel, cudaFuncAttributeMaxDynamicSharedMemorySize, MG_SMEM);

    auto WH = [&](int off) { return p_wh + (size_t)off * HH; };
    auto WL = [&](int off) { return p_wl + (size_t)off * HH; };

    // ---- 1. prep (wprep + convs + ln + CSR) ----
    {
        PrepArgs P{};
        const float* srcs[11] = {Wq, Wk, Wv, Wao, Wdv, Wf, Ws, Wvec, Wo, Wtrg, Wsrc};
        int ns[11]   = {256, 256, 256, 256, 256, 256, 512, 512, 768, 256, 256};
        int offs[11] = {OFF_WQ, OFF_WK, OFF_WV, OFF_WAO, OFF_WDV, OFF_WF,
                        OFF_WS, OFF_WVEC, OFF_WO, OFF_WTRG, OFF_WSRC};
        for (int i = 0; i < 11; i++) { P.wsrc[i] = srcs[i]; P.wN[i] = ns[i]; P.woff[i] = offs[i]; }
        P.f_ij = f_ij; P.vec = vec; P.x = x; P.ln_w = ln_w; P.ln_b = ln_b; P.dst = dst;
        prep_kernel<<<PREP_TOT, 256>>>(P);
    }

    // ---- 2. GEMM launch A: q,k,v,ff,vp,T,S (7 jobs, 1376 tiles) ----
    {
        GArgs A{};
        A.njobs = 7; A.mode = 0;
        A.jobs[0] = {p_xnh, p_xnl, WH(OFF_WQ),   WL(OFF_WQ),   p_zb, p_q,   HH,      2, 0, 0};
        A.jobs[1] = {p_xnh, p_xnl, WH(OFF_WK),   WL(OFF_WK),   p_zb, p_k,   HH,      2, 0, 32};
        A.jobs[2] = {p_xnh, p_xnl, WH(OFF_WV),   WL(OFF_WV),   p_zb, p_vv,  HH,      2, 0, 64};
        A.jobs[3] = {p_fijh, p_fijl, WH(OFF_WF), WL(OFF_WF),   bf,   p_ff,  HH,      2, 1, 96};
        A.jobs[4] = {p_vech, p_vecl, WH(OFF_WVEC), WL(OFF_WVEC), p_zb, p_vp, 2 * HH, 4, 0, 352};
        A.jobs[5] = {p_vech, p_vecl, WH(OFF_WTRG), WL(OFF_WTRG), p_zb, p_T,  HH,     2, 0, 864};
        A.jobs[6] = {p_vech, p_vecl, WH(OFF_WSRC), WL(OFF_WSRC), p_zb, p_S,  HH,     2, 0, 1120};
        gemm_kernel<<<1376, 256, MG_SMEM>>>(A);
    }

    // ---- 3. attention + wdot ----
    attn_wdot_kernel<<<64 + EE, 256>>>(src, dst, d_ij, r_ij, out_df);

    // ---- 4. v = vatt @ Wao ----
    {
        GArgs A{};
        A.njobs = 1; A.mode = 0;
        A.jobs[0] = {p_vath, p_vatl, WH(OFF_WAO), WL(OFF_WAO), p_zb, p_v, HH, 2, 0, 0};
        gemm_kernel<<<32, 256, MG_SMEM>>>(A);
    }

    // ---- 5. vj = silu(f_ij @ Wdv + bdv)*cut*v[src] -> bf16 hi/lo ----
    {
        GArgs A{};
        A.njobs = 1; A.mode = 1;
        A.jobs[0] = {p_fijh, p_fijl, WH(OFF_WDV), WL(OFF_WDV), bdv, nullptr, HH, 2, 0, 0};
        A.vsrc = p_v; A.srcidx = src; A.rij = r_ij; A.Oh = p_vjh; A.Ol = p_vjl;
        gemm_kernel<<<256, 256, MG_SMEM>>>(A);
    }

    // ---- 6. s12 = silu(v_j @ Ws + bs) ----
    {
        GArgs A{};
        A.njobs = 1; A.mode = 0;
        A.jobs[0] = {p_vjh, p_vjl, WH(OFF_WS), WL(OFF_WS), bs, p_s12, 2 * HH, 4, 1, 0};
        gemm_kernel<<<512, 256, MG_SMEM>>>(A);
    }

    // ---- 7. gather ----
    gather_kernel<<<BN, 256>>>(p_s12, vec, d_ij, src, out_dvec);

    // ---- 8. o = x_agg @ Wo + bo ----
    {
        GArgs A{};
        A.njobs = 1; A.mode = 0;
        A.jobs[0] = {p_xagh, p_xagl, WH(OFF_WO), WL(OFF_WO), bo, p_o, 3 * HH, 6, 0, 0};
        gemm_kernel<<<96, 256, MG_SMEM>>>(A);
    }

    // ---- 9. finalize ----
    finalize_kernel<<<BN, 256>>>(out_dx, out_dvec);
}

// round 7
// speedup vs baseline: 2.4614x; 1.1364x over previous
#include <cuda_runtime.h>
#include <cuda_bf16.h>
#include <cstdint>

// Problem constants
#define BB 8
#define NN 256
#define BN 2048          // BB*NN
#define EE 16384
#define HH 256
#define NHD 8
#define HD 32
#define VD 8

typedef __nv_bfloat16 bf16;

// ---------------- fp32 scratch ------------------------------------------------
__device__ float g_q   [BN*HH];
__device__ float g_k   [BN*HH];
__device__ float g_vv  [BN*HH];
__device__ float g_v   [BN*HH];
__device__ float g_vp  [BN*VD*2*HH];
__device__ float g_s12 [EE*2*HH];
__device__ float g_o   [BN*3*HH];
__device__ float g_T   [BN*VD*HH];
__device__ float g_S   [BN*VD*HH];
__device__ float g_ff  [EE*HH];
__device__ float g_zb  [3*HH];          // zero bias (static zero-init)

// ---------------- bf16 hi/lo scratch -----------------------------------------
__device__ bf16 g_xnh [BN*HH],    g_xnl [BN*HH];
__device__ bf16 g_vath[BN*HH],    g_vatl[BN*HH];
__device__ bf16 g_fijh[EE*HH],    g_fijl[EE*HH];
__device__ bf16 g_vjh [EE*HH],    g_vjl [EE*HH];
__device__ bf16 g_vech[BN*VD*HH], g_vecl[BN*VD*HH];
__device__ bf16 g_xagh[BN*HH],    g_xagl[BN*HH];
#define WROWS 3840
__device__ bf16 g_wh[WROWS*HH], g_wl[WROWS*HH];

// ---------------- CSR scratch -------------------------------------------------
__device__ int g_rowstart[BN + 1];
__device__ int g_elist[EE];

// weight row offsets within g_wh/g_wl
#define OFF_WQ   0
#define OFF_WK   256
#define OFF_WV   512
#define OFF_WAO  768
#define OFF_WDV  1024
#define OFF_WF   1280
#define OFF_WS   1536
#define OFF_WVEC 2048
#define OFF_WO   2560
#define OFF_WTRG 3328
#define OFF_WSRC 3584

__device__ __forceinline__ float silu_f(float x) { return x / (1.f + __expf(-x)); }
__device__ __forceinline__ float cut_f(float rr) {
    return (rr < 5.f) ? 0.5f * (cosf(rr * 0.6283185307179586f) + 1.f) : 0.f;
}

__device__ __forceinline__ uint32_t smem_u32(const void* p) {
    uint32_t a;
    asm("{ .reg .u64 t; cvta.to.shared.u64 t, %1; cvt.u32.u64 %0, t; }" : "=r"(a) : "l"(p));
    return a;
}

// ---------------- mma.sync / ldmatrix / cp.async wrappers --------------------
__device__ __forceinline__ void ldsm4(uint32_t* r, uint32_t addr) {
    asm volatile("ldmatrix.sync.aligned.m8n8.x4.shared.b16 {%0,%1,%2,%3}, [%4];"
                 : "=r"(r[0]), "=r"(r[1]), "=r"(r[2]), "=r"(r[3]) : "r"(addr));
}
__device__ __forceinline__ void mma_bf16(float* d, const uint32_t* a, const uint32_t* b) {
    asm volatile("mma.sync.aligned.m16n8k16.row.col.f32.bf16.bf16.f32 "
                 "{%0,%1,%2,%3}, {%4,%5,%6,%7}, {%8,%9}, {%0,%1,%2,%3};"
                 : "+f"(d[0]), "+f"(d[1]), "+f"(d[2]), "+f"(d[3])
                 : "r"(a[0]), "r"(a[1]), "r"(a[2]), "r"(a[3]), "r"(b[0]), "r"(b[1]));
}
#define CP_COMMIT() asm volatile("cp.async.commit_group;" ::: "memory")

// =============================================================================
// Unified job-table GEMM, 128x64 tiles (96KB smem -> 2 CTAs/SM).
// Mode 0: C = [silu](A@W^T + bias) fp32.
// Mode 1: vj epilogue silu(acc+bias)*cut(r[row])*v[src[row]][col] -> bf16 hi/lo.
// =============================================================================
struct GJob {
    const bf16 *Ah, *Al, *Bh, *Bl;
    const float* bias;
    float* C;
    int Nfull, colTiles, silu, tileOfs;
};
struct GArgs {
    GJob jobs[7];
    int njobs;
    int mode;
    const float* vsrc; const int* srcidx; const float* rij;
    bf16 *Oh, *Ol;
};

#define CHUNK_BYTES 49152
#define MG_SMEM (2 * CHUNK_BYTES)   // 96 KB

__device__ __forceinline__ void cp_tileA(uint32_t dst_s, const bf16* __restrict__ src,
                                         int rowbase, int kc, int tid)
{
    const char* g = (const char*)(src + (size_t)rowbase * HH + kc * 64);
#pragma unroll
    for (int it = 0; it < 4; it++) {
        int u   = tid + it * 256;       // 1024 units: 128 rows x 8
        int row = u >> 3;
        int ui  = u & 7;
        uint32_t off = row * 128 + ui * 16;
        off ^= (off >> 3) & 0x70;
        asm volatile("cp.async.cg.shared.global [%0], [%1], 16;"
                     :: "r"(dst_s + off), "l"(g + (size_t)row * 512 + ui * 16));
    }
}
__device__ __forceinline__ void cp_tileB(uint32_t dst_s, const bf16* __restrict__ src,
                                         int rowbase, int kc, int tid)
{
    const char* g = (const char*)(src + (size_t)rowbase * HH + kc * 64);
#pragma unroll
    for (int it = 0; it < 2; it++) {
        int u   = tid + it * 256;       // 512 units: 64 rows x 8
        int row = u >> 3;
        int ui  = u & 7;
        uint32_t off = row * 128 + ui * 16;
        off ^= (off >> 3) & 0x70;
        asm volatile("cp.async.cg.shared.global [%0], [%1], 16;"
                     :: "r"(dst_s + off), "l"(g + (size_t)row * 512 + ui * 16));
    }
}

__device__ __forceinline__ void cp_chunk(uint32_t sbase,
    const bf16* Ah, const bf16* Al, const bf16* Bh, const bf16* Bl,
    int rowA, int colB, int kc, int tid)
{
    cp_tileA(sbase,         Ah, rowA, kc, tid);
    cp_tileA(sbase + 16384, Al, rowA, kc, tid);
    cp_tileB(sbase + 32768, Bh, colB, kc, tid);
    cp_tileB(sbase + 40960, Bl, colB, kc, tid);
}

__global__ __launch_bounds__(256) void gemm_kernel(GArgs P)
{
    extern __shared__ uint8_t smem[];
    const int tid = threadIdx.x, wid = tid >> 5, lane = tid & 31;

    int j = 0;
#pragma unroll
    for (int jj = 1; jj < 7; jj++)
        if (jj < P.njobs && (int)blockIdx.x >= P.jobs[jj].tileOfs) j = jj;
    const GJob job = P.jobs[j];
    const int local = blockIdx.x - job.tileOfs;
    const int rowA = (local / job.colTiles) * 128;
    const int colB = (local % job.colTiles) * 64;

    const bf16* __restrict__ Ah = job.Ah;
    const bf16* __restrict__ Al = job.Al;
    const bf16* __restrict__ Bh = job.Bh;
    const bf16* __restrict__ Bl = job.Bl;

    const int wr = wid >> 1, wc = wid & 1;   // warp tile: 32 rows x 32 cols

    uint32_t aoff[2], boff[2];
#pragma unroll
    for (int i = 0; i < 2; i++)
        aoff[i] = (uint32_t)((wr * 32 + i * 16 + (lane & 15)) * 128 + (lane >> 4) * 16);
    {
        int grp = lane >> 3, lr = lane & 7;
#pragma unroll
        for (int j2 = 0; j2 < 2; j2++)
            boff[j2] = (uint32_t)((wc * 32 + j2 * 16 + (grp >> 1) * 8 + lr) * 128
                                  + (grp & 1) * 16);
    }

    const uint32_t sb = smem_u32(smem);

    float acc[2][4][4];
#pragma unroll
    for (int i = 0; i < 2; i++)
#pragma unroll
        for (int jj = 0; jj < 4; jj++)
#pragma unroll
            for (int r = 0; r < 4; r++) acc[i][jj][r] = 0.f;

    cp_chunk(sb,               Ah, Al, Bh, Bl, rowA, colB, 0, tid); CP_COMMIT();
    cp_chunk(sb + CHUNK_BYTES, Ah, Al, Bh, Bl, rowA, colB, 1, tid); CP_COMMIT();

    int buf = 0;
    for (int kc = 0; kc < 4; kc++) {
        if (kc < 3) asm volatile("cp.async.wait_group 1;" ::: "memory");
        else        asm volatile("cp.async.wait_group 0;" ::: "memory");
        __syncthreads();
        const uint32_t base = sb + buf * CHUNK_BYTES;
#pragma unroll
        for (int ks = 0; ks < 4; ks++) {
            const uint32_t kb = ks * 32;
            uint32_t ahf[2][4], alf[2][4], bhf[2][4], blf[2][4];
#pragma unroll
            for (int i = 0; i < 2; i++) {
                uint32_t o = aoff[i] + kb; o ^= (o >> 3) & 0x70;
                ldsm4(ahf[i], base + o);
                ldsm4(alf[i], base + 16384 + o);
            }
#pragma unroll
            for (int j2 = 0; j2 < 2; j2++) {
                uint32_t o = boff[j2] + kb; o ^= (o >> 3) & 0x70;
                ldsm4(bhf[j2], base + 32768 + o);
                ldsm4(blf[j2], base + 40960 + o);
            }
#pragma unroll
            for (int i = 0; i < 2; i++)
#pragma unroll
                for (int jj = 0; jj < 4; jj++) {
                    const uint32_t* b_hi = &bhf[jj >> 1][(jj & 1) * 2];
                    const uint32_t* b_lo = &blf[jj >> 1][(jj & 1) * 2];
                    mma_bf16(acc[i][jj], ahf[i], b_hi);
                    mma_bf16(acc[i][jj], ahf[i], b_lo);
                    mma_bf16(acc[i][jj], alf[i], b_hi);
                }
        }
        __syncthreads();
        if (kc + 2 <= 3) {
            cp_chunk(sb + buf * CHUNK_BYTES, Ah, Al, Bh, Bl, rowA, colB, kc + 2, tid);
            CP_COMMIT();
        }
        buf ^= 1;
    }

    const float* bias = job.bias;
    const int r0 = lane >> 2, c0 = (lane & 3) * 2;

    if (P.mode == 1) {
        __nv_bfloat162* OH = (__nv_bfloat162*)P.Oh;
        __nv_bfloat162* OL = (__nv_bfloat162*)P.Ol;
#pragma unroll
        for (int i = 0; i < 2; i++) {
            const int row0 = rowA + wr * 32 + i * 16 + r0;
            const int row1 = row0 + 8;
            const int s0 = P.srcidx[row0], s1i = P.srcidx[row1];
            const float cut0 = cut_f(P.rij[row0]);
            const float cut1 = cut_f(P.rij[row1]);
#pragma unroll
            for (int jj = 0; jj < 4; jj++) {
                const int gcol = colB + wc * 32 + jj * 8 + c0;
                const float b0 = bias[gcol], b1 = bias[gcol + 1];
                float v0 = silu_f(acc[i][jj][0] + b0) * cut0 * P.vsrc[(size_t)s0 * HH + gcol];
                float v1 = silu_f(acc[i][jj][1] + b1) * cut0 * P.vsrc[(size_t)s0 * HH + gcol + 1];
                float v2 = silu_f(acc[i][jj][2] + b0) * cut1 * P.vsrc[(size_t)s1i * HH + gcol];
                float v3 = silu_f(acc[i][jj][3] + b1) * cut1 * P.vsrc[(size_t)s1i * HH + gcol + 1];
                bf16 h0 = __float2bfloat16(v0), h1 = __float2bfloat16(v1);
                bf16 h2 = __float2bfloat16(v2), h3 = __float2bfloat16(v3);
                bf16 l0 = __float2bfloat16(v0 - __bfloat162float(h0));
                bf16 l1 = __float2bfloat16(v1 - __bfloat162float(h1));
                bf16 l2 = __float2bfloat16(v2 - __bfloat162float(h2));
                bf16 l3 = __float2bfloat16(v3 - __bfloat162float(h3));
                OH[(size_t)row0 * 128 + (gcol >> 1)] = __nv_bfloat162(h0, h1);
                OL[(size_t)row0 * 128 + (gcol >> 1)] = __nv_bfloat162(l0, l1);
                OH[(size_t)row1 * 128 + (gcol >> 1)] = __nv_bfloat162(h2, h3);
                OL[(size_t)row1 * 128 + (gcol >> 1)] = __nv_bfloat162(l2, l3);
            }
        }
    } else {
        float* __restrict__ C = job.C;
        const int Nfull = job.Nfull;
        const int do_silu = job.silu;
#pragma unroll
        for (int i = 0; i < 2; i++) {
            const int grow = rowA + wr * 32 + i * 16 + r0;
#pragma unroll
            for (int jj = 0; jj < 4; jj++) {
                const int gcol = colB + wc * 32 + jj * 8 + c0;
                float b0 = bias[gcol], b1 = bias[gcol + 1];
                float v0 = acc[i][jj][0] + b0, v1 = acc[i][jj][1] + b1;
                float v2 = acc[i][jj][2] + b0, v3 = acc[i][jj][3] + b1;
                if (do_silu) {
                    v0 = silu_f(v0); v1 = silu_f(v1); v2 = silu_f(v2); v3 = silu_f(v3);
                }
                *(float2*)(C + (size_t)grow * Nfull + gcol)       = make_float2(v0, v1);
                *(float2*)(C + (size_t)(grow + 8) * Nfull + gcol) = make_float2(v2, v3);
            }
        }
    }
}

// =============================================================================
// prep_kernel: wprep (8448) | conv fij (4096) | conv vec (4096) | ln (2048) | CSR (1)
// =============================================================================
struct PrepArgs {
    const float* wsrc[11]; int wN[11]; int woff[11];
    const float* f_ij; const float* vec; const float* x;
    const float* ln_w; const float* ln_b; const int* dst;
};

__device__ __forceinline__ void conv_body(int i, const float* __restrict__ in,
                                          bf16* hi, bf16* lo)
{
    float4 v = ((const float4*)in)[i];
    bf16 h0 = __float2bfloat16(v.x), h1 = __float2bfloat16(v.y);
    bf16 h2 = __float2bfloat16(v.z), h3 = __float2bfloat16(v.w);
    bf16 l0 = __float2bfloat16(v.x - __bfloat162float(h0));
    bf16 l1 = __float2bfloat16(v.y - __bfloat162float(h1));
    bf16 l2 = __float2bfloat16(v.z - __bfloat162float(h2));
    bf16 l3 = __float2bfloat16(v.w - __bfloat162float(h3));
    __nv_bfloat162* hp = (__nv_bfloat162*)hi;
    __nv_bfloat162* lp = (__nv_bfloat162*)lo;
    hp[2 * i]     = __nv_bfloat162(h0, h1);
    hp[2 * i + 1] = __nv_bfloat162(h2, h3);
    lp[2 * i]     = __nv_bfloat162(l0, l1);
    lp[2 * i + 1] = __nv_bfloat162(l2, l3);
}

#define PREP_WP   8448
#define PREP_CF   4096
#define PREP_CV   4096
#define PREP_LN   2048
#define PREP_TOT  (PREP_WP + PREP_CF + PREP_CV + PREP_LN + 1)

__global__ __launch_bounds__(256) void prep_kernel(PrepArgs P)
{
    __shared__ int csr_s[BN];
    __shared__ float red[8];
    int bx = blockIdx.x;
    const int t = threadIdx.x;

    if (bx < PREP_WP) {               // weight prep
        int w = bx / 768, n = bx % 768;
        if (n < P.wN[w]) {
            float v = P.wsrc[w][(size_t)t * P.wN[w] + n];
            bf16 h = __float2bfloat16(v);
            bf16 l = __float2bfloat16(v - __bfloat162float(h));
            size_t o = (size_t)(P.woff[w] + n) * HH + t;
            g_wh[o] = h; g_wl[o] = l;
        }
        return;
    }
    bx -= PREP_WP;
    if (bx < PREP_CF) { conv_body(bx * 256 + t, P.f_ij, g_fijh, g_fijl); return; }
    bx -= PREP_CF;
    if (bx < PREP_CV) { conv_body(bx * 256 + t, P.vec, g_vech, g_vecl); return; }
    bx -= PREP_CV;
    if (bx < PREP_LN) {               // LayerNorm
        int n = bx;
        float v = P.x[n * HH + t];
        float s = v;
#pragma unroll
        for (int o = 16; o; o >>= 1) s += __shfl_xor_sync(0xffffffffu, s, o);
        if ((t & 31) == 0) red[t >> 5] = s;
        __syncthreads();
        float tot = 0.f;
#pragma unroll
        for (int i = 0; i < 8; i++) tot += red[i];
        float mu = tot * (1.f / HH);
        float dv = v - mu;
        float s2 = dv * dv;
#pragma unroll
        for (int o = 16; o; o >>= 1) s2 += __shfl_xor_sync(0xffffffffu, s2, o);
        __syncthreads();
        if ((t & 31) == 0) red[t >> 5] = s2;
        __syncthreads();
        float var = 0.f;
#pragma unroll
        for (int i = 0; i < 8; i++) var += red[i];
        var *= (1.f / HH);
        float xn = dv * rsqrtf(var + 1e-5f) * P.ln_w[t] + P.ln_b[t];
        bf16 hh2 = __float2bfloat16(xn);
        g_xnh[n * HH + t] = hh2;
        g_xnl[n * HH + t] = __float2bfloat16(xn - __bfloat162float(hh2));
        return;
    }

    // ---- CSR build (single block) ----
    for (int i = t; i < BN; i += 256) csr_s[i] = 0;
    __syncthreads();
    const int4* d4 = (const int4*)P.dst;
#pragma unroll
    for (int i = 0; i < 16; i++) {
        int4 v = d4[t * 16 + i];
        atomicAdd(&csr_s[v.x], 1); atomicAdd(&csr_s[v.y], 1);
        atomicAdd(&csr_s[v.z], 1); atomicAdd(&csr_s[v.w], 1);
    }
    __syncthreads();
    for (int d = 1; d < BN; d <<= 1) {
        for (int i = t; i < BN / (2 * d); i += 256) {
            int idx = (i + 1) * 2 * d - 1;
            csr_s[idx] += csr_s[idx - d];
        }
        __syncthreads();
    }
    if (t == 0) { g_rowstart[BN] = csr_s[BN - 1]; csr_s[BN - 1] = 0; }
    __syncthreads();
    for (int d = BN / 2; d >= 1; d >>= 1) {
        for (int i = t; i < BN / (2 * d); i += 256) {
            int idx = (i + 1) * 2 * d - 1;
            int a = csr_s[idx - d];
            csr_s[idx - d] = csr_s[idx];
            csr_s[idx] += a;
        }
        __syncthreads();
    }
    for (int i = t; i < BN; i += 256) g_rowstart[i] = csr_s[i];
    __syncthreads();
#pragma unroll
    for (int i = 0; i < 16; i++) {
        int4 v = d4[t * 16 + i];
        int e = t * 64 + i * 4;
        int p0 = atomicAdd(&csr_s[v.x], 1); g_elist[p0] = e;
        int p1 = atomicAdd(&csr_s[v.y], 1); g_elist[p1] = e + 1;
        int p2 = atomicAdd(&csr_s[v.z], 1); g_elist[p2] = e + 2;
        int p3 = atomicAdd(&csr_s[v.w], 1); g_elist[p3] = e + 3;
    }
}

// =============================================================================
// attn (blocks 0..63) + wdot (blocks 64..64+EE)
// =============================================================================
__global__ __launch_bounds__(256) void attn_wdot_kernel(
    const int* __restrict__ src, const int* __restrict__ dst,
    const float* __restrict__ dij, float* __restrict__ df)
{
    __shared__ float ks[64][32];
    __shared__ float vs[64][32];
    __shared__ float dsh[VD];

    if (blockIdx.x < 64) {
        int b = blockIdx.x >> 3;
        int hd = blockIdx.x & 7;
        int i = threadIdx.x;
        float qr[32];
        const float* qrow = g_q + (size_t)(b * NN + i) * HH + hd * HD;
#pragma unroll
        for (int d = 0; d < 32; d++) qr[d] = qrow[d];
        float acc[32];
#pragma unroll
        for (int d = 0; d < 32; d++) acc[d] = 0.f;
        const float scale = rsqrtf((float)HD);

        for (int j0 = 0; j0 < NN; j0 += 64) {
            __syncthreads();
            for (int l = threadIdx.x; l < 512; l += 256) {
                int jr = l >> 3;
                int dc = (l & 7) * 4;
                size_t base = (size_t)(b * NN + j0 + jr) * HH + hd * HD + dc;
                *(float4*)&ks[jr][dc] = *(const float4*)&g_k[base];
                *(float4*)&vs[jr][dc] = *(const float4*)&g_vv[base];
            }
            __syncthreads();
            for (int j = 0; j < 64; j++) {
                float s = 0.f;
#pragma unroll
                for (int d = 0; d < 32; d++) s += qr[d] * ks[j][d];
                s = silu_f(s * scale);
#pragma unroll
                for (int d = 0; d < 32; d++) acc[d] += s * vs[j][d];
            }
        }
        size_t base = (size_t)(b * NN + i) * HH + hd * HD;
#pragma unroll
        for (int d = 0; d < 32; d++) {
            float val = acc[d] * (1.f / NN);
            bf16 h2 = __float2bfloat16(val);
            g_vath[base + d] = h2;
            g_vatl[base + d] = __float2bfloat16(val - __bfloat162float(h2));
        }
        return;
    }

    int e = blockIdx.x - 64;
    int h = threadIdx.x;
    if (h < VD) dsh[h] = dij[e * VD + h];
    __syncthreads();
    int s = src[e], tt = dst[e];
    float tv[VD], sv[VD];
    float pT = 0.f, pS = 0.f;
#pragma unroll
    for (int vd = 0; vd < VD; vd++) {
        tv[vd] = g_T[(size_t)(tt * VD + vd) * HH + h];
        sv[vd] = g_S[(size_t)(s * VD + vd) * HH + h];
        pT += tv[vd] * dsh[vd];
        pS += sv[vd] * dsh[vd];
    }
    float wd = 0.f;
#pragma unroll
    for (int vd = 0; vd < VD; vd++)
        wd += (tv[vd] - pT * dsh[vd]) * (sv[vd] - pS * dsh[vd]);
    df[(size_t)e * HH + h] = g_ff[(size_t)e * HH + h] * wd;
}

// ======================= gather: x_agg + dvec (no atomics) ===================
__global__ __launch_bounds__(256) void gather_kernel(
    const float* __restrict__ s12, const float* __restrict__ vec,
    const float* __restrict__ dij, const int* __restrict__ src,
    float* __restrict__ dvec_out)
{
    int n = blockIdx.x, h = threadIdx.x;
    int beg = g_rowstart[n], end = g_rowstart[n + 1];
    float xa = 0.f;
    float dv[VD];
#pragma unroll
    for (int vd = 0; vd < VD; vd++) dv[vd] = 0.f;

    for (int i = beg; i < end; i++) {
        int e = g_elist[i];
        int s = src[e];
        float vje = __bfloat162float(g_vjh[(size_t)e * HH + h]) +
                    __bfloat162float(g_vjl[(size_t)e * HH + h]);
        xa += vje;
        float s1  = s12[(size_t)e * (2 * HH) + h];
        float s2v = s12[(size_t)e * (2 * HH) + HH + h];
#pragma unroll
        for (int vd = 0; vd < VD; vd++)
            dv[vd] += vec[(size_t)s * (VD * HH) + vd * HH + h] * s1
                    + s2v * dij[e * VD + vd];
    }
    bf16 hh = __float2bfloat16(xa);
    g_xagh[n * HH + h] = hh;
    g_xagl[n * HH + h] = __float2bfloat16(xa - __bfloat162float(hh));
#pragma unroll
    for (int vd = 0; vd < VD; vd++)
        dvec_out[(size_t)n * (VD * HH) + vd * HH + h] = dv[vd];
}

// ======================= finalize ============================================
__global__ __launch_bounds__(256) void finalize_kernel(float* __restrict__ dx,
                                                       float* __restrict__ dvec)
{
    int n = blockIdx.x, h = threadIdx.x;
    float o1 = g_o[(size_t)n * (3 * HH) + h];
    float o2 = g_o[(size_t)n * (3 * HH) + HH + h];
    float o3 = g_o[(size_t)n * (3 * HH) + 2 * HH + h];
    float vsum = 0.f;
#pragma unroll
    for (int vd = 0; vd < VD; vd++)
        vsum += g_vp[(size_t)(n * VD + vd) * (2 * HH) + h];
    dx[n * HH + h] = vsum * o2 + o3;
#pragma unroll
    for (int vd = 0; vd < VD; vd++) {
        float vec3 = g_vp[(size_t)(n * VD + vd) * (2 * HH) + HH + h];
        dvec[(size_t)n * (VD * HH) + vd * HH + h] += vec3 * o1;
    }
}

// ======================= launcher ============================================
extern "C" void kernel_launch(void* const* d_in, const int* in_sizes, int n_in,
                              void* d_out, int out_size)
{
    const float* x    = (const float*)d_in[0];
    const float* vec  = (const float*)d_in[1];
    const int*   ei   = (const int*)d_in[2];
    const float* r_ij = (const float*)d_in[3];
    const float* f_ij = (const float*)d_in[4];
    const float* d_ij = (const float*)d_in[5];
    const float* ln_w = (const float*)d_in[7];
    const float* ln_b = (const float*)d_in[8];
    const float* Wq   = (const float*)d_in[9];
    const float* Wk   = (const float*)d_in[10];
    const float* Wv   = (const float*)d_in[11];
    const float* Wao  = (const float*)d_in[12];
    const float* Wvec = (const float*)d_in[13];
    const float* Wdv  = (const float*)d_in[14];
    const float* bdv  = (const float*)d_in[15];
    const float* Ws   = (const float*)d_in[16];
    const float* bs   = (const float*)d_in[17];
    const float* Wo   = (const float*)d_in[18];
    const float* bo   = (const float*)d_in[19];
    const float* Wf   = (const float*)d_in[20];
    const float* bf   = (const float*)d_in[21];
    const float* Wsrc = (const float*)d_in[22];
    const float* Wtrg = (const float*)d_in[23];

    const int* src = ei;
    const int* dst = ei + EE;

    float* out      = (float*)d_out;
    float* out_dx   = out;
    float* out_dvec = out + (size_t)BN * HH;
    float* out_df   = out_dvec + (size_t)BN * VD * HH;

    float *p_q, *p_k, *p_vv, *p_v, *p_vp, *p_s12, *p_o, *p_T, *p_S, *p_ff, *p_zb;
    bf16 *p_xnh, *p_xnl, *p_vath, *p_vatl, *p_fijh, *p_fijl, *p_vjh, *p_vjl,
         *p_vech, *p_vecl, *p_xagh, *p_xagl, *p_wh, *p_wl;
    cudaGetSymbolAddress((void**)&p_q,    g_q);
    cudaGetSymbolAddress((void**)&p_k,    g_k);
    cudaGetSymbolAddress((void**)&p_vv,   g_vv);
    cudaGetSymbolAddress((void**)&p_v,    g_v);
    cudaGetSymbolAddress((void**)&p_vp,   g_vp);
    cudaGetSymbolAddress((void**)&p_s12,  g_s12);
    cudaGetSymbolAddress((void**)&p_o,    g_o);
    cudaGetSymbolAddress((void**)&p_T,    g_T);
    cudaGetSymbolAddress((void**)&p_S,    g_S);
    cudaGetSymbolAddress((void**)&p_ff,   g_ff);
    cudaGetSymbolAddress((void**)&p_zb,   g_zb);
    cudaGetSymbolAddress((void**)&p_xnh,  g_xnh);
    cudaGetSymbolAddress((void**)&p_xnl,  g_xnl);
    cudaGetSymbolAddress((void**)&p_vath, g_vath);
    cudaGetSymbolAddress((void**)&p_vatl, g_vatl);
    cudaGetSymbolAddress((void**)&p_fijh, g_fijh);
    cudaGetSymbolAddress((void**)&p_fijl, g_fijl);
    cudaGetSymbolAddress((void**)&p_vjh,  g_vjh);
    cudaGetSymbolAddress((void**)&p_vjl,  g_vjl);
    cudaGetSymbolAddress((void**)&p_vech, g_vech);
    cudaGetSymbolAddress((void**)&p_vecl, g_vecl);
    cudaGetSymbolAddress((void**)&p_xagh, g_xagh);
    cudaGetSymbolAddress((void**)&p_xagl, g_xagl);
    cudaGetSymbolAddress((void**)&p_wh,   g_wh);
    cudaGetSymbolAddress((void**)&p_wl,   g_wl);

    cudaFuncSetAttribute(gemm_kernel, cudaFuncAttributeMaxDynamicSharedMemorySize, MG_SMEM);

    auto WH = [&](int off) { return p_wh + (size_t)off * HH; };
    auto WL = [&](int off) { return p_wl + (size_t)off * HH; };

    // ---- 1. prep (wprep + convs + ln + CSR) ----
    {
        PrepArgs P{};
        const float* srcs[11] = {Wq, Wk, Wv, Wao, Wdv, Wf, Ws, Wvec, Wo, Wtrg, Wsrc};
        int ns[11]   = {256, 256, 256, 256, 256, 256, 512, 512, 768, 256, 256};
        int offs[11] = {OFF_WQ, OFF_WK, OFF_WV, OFF_WAO, OFF_WDV, OFF_WF,
                        OFF_WS, OFF_WVEC, OFF_WO, OFF_WTRG, OFF_WSRC};
        for (int i = 0; i < 11; i++) { P.wsrc[i] = srcs[i]; P.wN[i] = ns[i]; P.woff[i] = offs[i]; }
        P.f_ij = f_ij; P.vec = vec; P.x = x; P.ln_w = ln_w; P.ln_b = ln_b; P.dst = dst;
        prep_kernel<<<PREP_TOT, 256>>>(P);
    }

    // ---- 2. GEMM launch A: q,k,v,ff,vp,T,S (7 jobs, 2752 tiles of 128x64) ----
    {
        GArgs A{};
        A.njobs = 7; A.mode = 0;
        A.jobs[0] = {p_xnh, p_xnl, WH(OFF_WQ),   WL(OFF_WQ),   p_zb, p_q,   HH,      4, 0, 0};
        A.jobs[1] = {p_xnh, p_xnl, WH(OFF_WK),   WL(OFF_WK),   p_zb, p_k,   HH,      4, 0, 64};
        A.jobs[2] = {p_xnh, p_xnl, WH(OFF_WV),   WL(OFF_WV),   p_zb, p_vv,  HH,      4, 0, 128};
        A.jobs[3] = {p_fijh, p_fijl, WH(OFF_WF), WL(OFF_WF),   bf,   p_ff,  HH,      4, 1, 192};
        A.jobs[4] = {p_vech, p_vecl, WH(OFF_WVEC), WL(OFF_WVEC), p_zb, p_vp, 2 * HH, 8, 0, 704};
        A.jobs[5] = {p_vech, p_vecl, WH(OFF_WTRG), WL(OFF_WTRG), p_zb, p_T,  HH,     4, 0, 1728};
        A.jobs[6] = {p_vech, p_vecl, WH(OFF_WSRC), WL(OFF_WSRC), p_zb, p_S,  HH,     4, 0, 2240};
        gemm_kernel<<<2752, 256, MG_SMEM>>>(A);
    }

    // ---- 3. attention + wdot ----
    attn_wdot_kernel<<<64 + EE, 256>>>(src, dst, d_ij, out_df);

    // ---- 4. v = vatt @ Wao (64 tiles) ----
    {
        GArgs A{};
        A.njobs = 1; A.mode = 0;
        A.jobs[0] = {p_vath, p_vatl, WH(OFF_WAO), WL(OFF_WAO), p_zb, p_v, HH, 4, 0, 0};
        gemm_kernel<<<64, 256, MG_SMEM>>>(A);
    }

    // ---- 5. vj = silu(f_ij @ Wdv + bdv)*cut*v[src] -> bf16 hi/lo (512 tiles) ----
    {
        GArgs A{};
        A.njobs = 1; A.mode = 1;
        A.jobs[0] = {p_fijh, p_fijl, WH(OFF_WDV), WL(OFF_WDV), bdv, nullptr, HH, 4, 0, 0};
        A.vsrc = p_v; A.srcidx = src; A.rij = r_ij; A.Oh = p_vjh; A.Ol = p_vjl;
        gemm_kernel<<<512, 256, MG_SMEM>>>(A);
    }

    // ---- 6. s12 = silu(v_j @ Ws + bs) (1024 tiles) ----
    {
        GArgs A{};
        A.njobs = 1; A.mode = 0;
        A.jobs[0] = {p_vjh, p_vjl, WH(OFF_WS), WL(OFF_WS), bs, p_s12, 2 * HH, 8, 1, 0};
        gemm_kernel<<<1024, 256, MG_SMEM>>>(A);
    }

    // ---- 7. gather ----
    gather_kernel<<<BN, 256>>>(p_s12, vec, d_ij, src, out_dvec);

    // ---- 8. o = x_agg @ Wo + bo (192 tiles) ----
    {
        GArgs A{};
        A.njobs = 1; A.mode = 0;
        A.jobs[0] = {p_xagh, p_xagl, WH(OFF_WO), WL(OFF_WO), bo, p_o, 3 * HH, 12, 0, 0};
        gemm_kernel<<<192, 256, MG_SMEM>>>(A);
    }

    // ---- 9. finalize ----
    finalize_kernel<<<BN, 256>>>(out_dx, out_dvec);
}